// round 12
// baseline (speedup 1.0000x reference)
#include <cuda_runtime.h>
#include <cuda_bf16.h>
#include <math.h>
#include <stdint.h>

// Problem constants
#define BB   4
#define NN   30000
#define FFd  60000
#define NNZk 720000

static const size_t SZ_V = (size_t)BB * NN * 128;   // 15,360,000
static const size_t SZ_F = (size_t)BB * FFd * 128;  // 30,720,000

// ---------------- scratch (static device arrays) ----------------
__device__ float  g_xin[15360000];                    // elu(v) f32 (spbmm1 src)
__device__ __nv_bfloat16 g_xinhi[15360000], g_xinlo[15360000];
__device__ __nv_bfloat16 g_finhi[30720000], g_finlo[30720000];  // elu(f) bf16 only
__device__ float  g_t0 [30720000];                    // spbmm1 out f32
__device__ float  g_g  [30720000];                    // elu(f_out) f32 (spbmm2 src)
__device__ float  g_t1 [15360000];                    // spbmm2 out f32
__device__ double g_stats0[512];
__device__ double g_stats1[512];
__device__ __nv_bfloat16 g_w0hi[32768], g_w0lo[32768];
__device__ __nv_bfloat16 g_w1hi[32768], g_w1lo[32768];
__device__ float  g_b0p[128];
__device__ float  g_b1p[128];

// ---------------- helpers ----------------
__device__ __forceinline__ uint32_t smem_u32(const void* p) {
    uint32_t a;
    asm("{ .reg .u64 t; cvta.to.shared.u64 t, %1; cvt.u32.u64 %0, t; }" : "=r"(a) : "l"(p));
    return a;
}

#define SW128(o) ((o) ^ (((o) >> 3) & 0x70))

__device__ __forceinline__ float elu1(float x) { return x > 0.f ? x : expm1f(x); }

__device__ __forceinline__ void ldsm4(uint32_t* d, uint32_t addr) {
    asm volatile("ldmatrix.sync.aligned.m8n8.x4.shared.b16 {%0,%1,%2,%3}, [%4];"
                 : "=r"(d[0]), "=r"(d[1]), "=r"(d[2]), "=r"(d[3]) : "r"(addr));
}

__device__ __forceinline__ void mma16816(float* c, const uint32_t* a, uint32_t b0, uint32_t b1) {
    asm volatile("mma.sync.aligned.m16n8k16.row.col.f32.bf16.bf16.f32 "
                 "{%0,%1,%2,%3}, {%4,%5,%6,%7}, {%8,%9}, {%0,%1,%2,%3};"
                 : "+f"(c[0]), "+f"(c[1]), "+f"(c[2]), "+f"(c[3])
                 : "r"(a[0]), "r"(a[1]), "r"(a[2]), "r"(a[3]), "r"(b0), "r"(b1));
}

__device__ __forceinline__ void cpa16(uint32_t smem, const uint4* gptr, int sz) {
    asm volatile("cp.async.cg.shared.global [%0], [%1], 16, %2;"
                 :: "r"(smem), "l"(gptr), "r"(sz) : "memory");
}
#define CP_COMMIT() asm volatile("cp.async.commit_group;" ::: "memory")
template <int N> __device__ __forceinline__ void cp_wait() {
    asm volatile("cp.async.wait_group %0;" :: "n"(N) : "memory");
}

__device__ __forceinline__ void split4_pack(float4 v, uint2& hi, uint2& lo) {
    __nv_bfloat16 h[4], l[4];
    h[0] = __float2bfloat16(v.x); l[0] = __float2bfloat16(v.x - __bfloat162float(h[0]));
    h[1] = __float2bfloat16(v.y); l[1] = __float2bfloat16(v.y - __bfloat162float(h[1]));
    h[2] = __float2bfloat16(v.z); l[2] = __float2bfloat16(v.z - __bfloat162float(h[2]));
    h[3] = __float2bfloat16(v.w); l[3] = __float2bfloat16(v.w - __bfloat162float(h[3]));
    hi = *(const uint2*)h; lo = *(const uint2*)l;
}

// ---------------- zero kernels ----------------
__global__ void zero_stats_kernel() {
    int i = threadIdx.x;
    ((double2*)g_stats0)[i] = make_double2(0.0, 0.0);
    ((double2*)g_stats1)[i] = make_double2(0.0, 0.0);
}

template <int WHICH>
__global__ void zero_slice_kernel(int batch) {
    int i = blockIdx.x * blockDim.x + threadIdx.x;
    int n4 = (WHICH == 0) ? FFd * 32 : NN * 32;
    if (i >= n4) return;
    float4* p = (WHICH == 0) ? ((float4*)g_t0 + (size_t)batch * (FFd * 32))
                             : ((float4*)g_t1 + (size_t)batch * (NN * 32));
    p[i] = make_float4(0.f, 0.f, 0.f, 0.f);
}

// ---------------- fused elu + column stats + bf16 hi/lo emit -----------------------
template <int WHICH>
__global__ void elu_stats_kernel(const float4* __restrict__ in, int n4) {
    __shared__ float rs[8][32][4], rq[8][32][4];
    double* stats = (WHICH == 0) ? g_stats1 : g_stats0;
    uint2* outhi = (uint2*)(WHICH == 0 ? g_xinhi : g_finhi);
    uint2* outlo = (uint2*)(WHICH == 0 ? g_xinlo : g_finlo);
    int tid = threadIdx.x;
    float s[4] = {0.f, 0.f, 0.f, 0.f}, q2[4] = {0.f, 0.f, 0.f, 0.f};
    for (int i = blockIdx.x * blockDim.x + tid; i < n4; i += gridDim.x * blockDim.x) {
        float4 v = in[i];
        v.x = elu1(v.x); v.y = elu1(v.y); v.z = elu1(v.z); v.w = elu1(v.w);
        if (WHICH == 0) ((float4*)g_xin)[i] = v;
        uint2 hi, lo; split4_pack(v, hi, lo);
        outhi[i] = hi; outlo[i] = lo;
        s[0] += v.x; q2[0] += v.x * v.x;
        s[1] += v.y; q2[1] += v.y * v.y;
        s[2] += v.z; q2[2] += v.z * v.z;
        s[3] += v.w; q2[3] += v.w * v.w;
    }
    int cq = tid & 31, rt = tid >> 5;
#pragma unroll
    for (int e = 0; e < 4; e++) { rs[rt][cq][e] = s[e]; rq[rt][cq][e] = q2[e]; }
    __syncthreads();
    if (tid < 128) {
        int e = tid & 3, c = tid >> 2;
        float t = 0.f;
#pragma unroll
        for (int r = 0; r < 8; r++) t += rs[r][c][e];
        atomicAdd(&stats[c * 4 + e], (double)t);
    } else {
        int t2 = tid - 128;
        int e = t2 & 3, c = t2 >> 2;
        float t = 0.f;
#pragma unroll
        for (int r = 0; r < 8; r++) t += rq[r][c][e];
        atomicAdd(&stats[256 + c * 4 + e], (double)t);
    }
}

// ---- second-half stats over t0 / t1 (stats only; concat cols 128..255) ----
template <int PASS>
__global__ void halfstats_kernel(int n4) {
    __shared__ float rs[8][32][4], rq[8][32][4];
    const float4* src = (PASS == 0) ? (const float4*)g_t0 : (const float4*)g_t1;
    double* stats = (PASS == 0) ? g_stats0 : g_stats1;
    int tid = threadIdx.x;
    float s[4] = {0.f, 0.f, 0.f, 0.f}, q2[4] = {0.f, 0.f, 0.f, 0.f};
    for (int i = blockIdx.x * blockDim.x + tid; i < n4; i += gridDim.x * blockDim.x) {
        float4 v = src[i];
        s[0] += v.x; q2[0] += v.x * v.x;
        s[1] += v.y; q2[1] += v.y * v.y;
        s[2] += v.z; q2[2] += v.z * v.z;
        s[3] += v.w; q2[3] += v.w * v.w;
    }
    int cq = tid & 31, rt = tid >> 5;
#pragma unroll
    for (int e = 0; e < 4; e++) { rs[rt][cq][e] = s[e]; rq[rt][cq][e] = q2[e]; }
    __syncthreads();
    if (tid < 128) {
        int e = tid & 3, c = tid >> 2;
        float t = 0.f;
#pragma unroll
        for (int r = 0; r < 8; r++) t += rs[r][c][e];
        atomicAdd(&stats[128 + c * 4 + e], (double)t);
    } else {
        int t2 = tid - 128;
        int e = t2 & 3, c = t2 >> 2;
        float t = 0.f;
#pragma unroll
        for (int r = 0; r < 8; r++) t += rq[r][c][e];
        atomicAdd(&stats[384 + c * 4 + e], (double)t);
    }
}

// ---------------- sparse COO spmm, one batch per launch (L2-resident dst) ----------
template <int PASS>
__global__ void spbmm_kernel(const int* __restrict__ rows, const int* __restrict__ cols,
                             const float* __restrict__ vals, int batch) {
    int gw   = (blockIdx.x * blockDim.x + threadIdx.x) >> 5;
    int lane = threadIdx.x & 31;
    int e    = gw * 4 + (lane >> 3);
    int q    = lane & 7;
    if (e >= NNZk) return;
    int   r = rows[e];
    int   c = cols[e];
    float v = vals[e];
    const float* src = (PASS == 0) ? (g_xin + (size_t)batch * NN * 128)
                                   : (g_g   + (size_t)batch * FFd * 128);
    float*       dst = (PASS == 0) ? (g_t0 + (size_t)batch * FFd * 128)
                                   : (g_t1 + (size_t)batch * NN * 128);
    float4 x = *(const float4*)(src + (size_t)c * 32 + q * 4);
    x.x *= v; x.y *= v; x.z *= v; x.w *= v;
    asm volatile("red.global.add.v4.f32 [%0], {%1, %2, %3, %4};"
                 :: "l"(dst + (size_t)r * 32 + q * 4), "f"(x.x), "f"(x.y), "f"(x.z), "f"(x.w)
                 : "memory");
}

// ---- finalize BN + fold into linear; emit bf16 hi/lo weights + fused bias ----
template <int PASS>
__global__ void finalize_fold_kernel(const float* __restrict__ gamma, const float* __restrict__ beta,
                                     const float* __restrict__ w, const float* __restrict__ bias,
                                     int M) {
    __shared__ float a_s[256], sh_s[256];
    const double* stats = (PASS == 0) ? g_stats0 : g_stats1;
    __nv_bfloat16* whi = (PASS == 0) ? g_w0hi : g_w1hi;
    __nv_bfloat16* wlo = (PASS == 0) ? g_w0lo : g_w1lo;
    float* bp = (PASS == 0) ? g_b0p : g_b1p;
    int j = threadIdx.x;
    double invM = 1.0 / (double)M;
    double mu   = stats[j] * invM;
    double var  = stats[256 + j] * invM - mu * mu;
    float a  = gamma[j] * rsqrtf((float)var + 1e-5f);
    float sh = beta[j] - (float)mu * a;
    a_s[j] = a; sh_s[j] = sh;
    __syncthreads();
    for (int idx = j; idx < 128 * 256; idx += 256) {
        float wv = w[idx] * a_s[idx & 255];
        __nv_bfloat16 hi = __float2bfloat16(wv);
        __nv_bfloat16 lo = __float2bfloat16(wv - __bfloat162float(hi));
        whi[idx] = hi; wlo[idx] = lo;
    }
    if (j < 128) {
        float s = bias[j];
        const float* wr = w + j * 256;
        for (int q = 0; q < 256; q++) s += sh_s[q] * wr[q];
        bp[j] = s;
    }
}

// ---------------- HMMA bf16 GEMM, double-buffered ----------------------------------
// K chunks of 32; smem row = 128B [hi 64B | lo 64B], SW128-swizzled.
// A0 (fin/xin) pre-split bf16 -> cp.async; A1 (t0/t1) f32 -> LDG + split + STS.
#define SMEM_SZ (1024 + 2 * 32768)   // 66560

template <int PASS>
__global__ void __launch_bounds__(256, 2)
gemm_mma_kernel(const float* __restrict__ resid, float* __restrict__ out, int M) {
    extern __shared__ char smem[];
    const uint4* A0hi = (const uint4*)(PASS == 0 ? g_finhi : g_xinhi);
    const uint4* A0lo = (const uint4*)(PASS == 0 ? g_finlo : g_xinlo);
    const float* A1f  = (PASS == 0) ? g_t0 : g_t1;
    const uint4* Whi  = (const uint4*)(PASS == 0 ? g_w0hi : g_w1hi);
    const uint4* Wlo  = (const uint4*)(PASS == 0 ? g_w0lo : g_w1lo);
    const float* bp = (PASS == 0) ? g_b0p : g_b1p;

    uint32_t sb = smem_u32(smem);
    int tid  = threadIdx.x;
    int wid  = tid >> 5;
    int lane = tid & 31;
    int m0   = blockIdx.x * 128;
    int wm   = (wid & 3) * 32;
    int wn   = (wid >> 2) * 64;

    if (tid < 128) *(float*)(smem + tid * 4) = bp[tid];

    float acc[2][8][4];
#pragma unroll
    for (int mt = 0; mt < 2; mt++)
#pragma unroll
        for (int nt = 0; nt < 8; nt++)
#pragma unroll
            for (int e = 0; e < 4; e++) acc[mt][nt][e] = 0.f;

    int lrow = (lane & 7) + ((lane >> 3) & 1) * 8;
    int lkg  = lane >> 4;

    auto stage_chunk = [&](int ch, int s) {
        uint32_t abase = sb + 1024 + s * 32768;
        uint32_t wbase = abase + 16384;
        if (ch < 4) {
            int cb = ch * 4;
#pragma unroll
            for (int i = 0; i < 4; i++) {
                int idx = tid + i * 256;
                int row = idx >> 3;
                int u   = idx & 7;
                uint32_t soff = SW128((uint32_t)(row * 128 + u * 16));
                bool ok = (m0 + row < M);
                size_t gi = ok ? ((size_t)(m0 + row) * 16 + cb + (u & 3)) : 0;
                cpa16(abase + soff, ((u < 4) ? A0hi : A0lo) + gi, ok ? 16 : 0);
            }
        } else {
            int kb = (ch & 3) * 32;
#pragma unroll
            for (int i = 0; i < 2; i++) {
                int idx2 = tid + i * 256;       // 0..511
                int row  = idx2 >> 2;           // 0..127
                int eg   = idx2 & 3;            // element-granule 0..3 (8 f32)
                float4 a0 = make_float4(0.f, 0.f, 0.f, 0.f), a1 = a0;
                if (m0 + row < M) {
                    const float* ap = A1f + (size_t)(m0 + row) * 128 + kb + eg * 8;
                    a0 = *(const float4*)ap;
                    a1 = *(const float4*)(ap + 4);
                }
                uint2 h0, l0, h1, l1;
                split4_pack(a0, h0, l0);
                split4_pack(a1, h1, l1);
                uint4 hi = make_uint4(h0.x, h0.y, h1.x, h1.y);
                uint4 lo = make_uint4(l0.x, l0.y, l1.x, l1.y);
                *(uint4*)(smem + 1024 + s * 32768 + SW128((uint32_t)(row * 128 + eg * 16))) = hi;
                *(uint4*)(smem + 1024 + s * 32768 + SW128((uint32_t)(row * 128 + (4 + eg) * 16))) = lo;
            }
        }
        int wb = ch * 4;
#pragma unroll
        for (int i = 0; i < 4; i++) {
            int idx = tid + i * 256;
            int row = idx >> 3;
            int u   = idx & 7;
            uint32_t soff = SW128((uint32_t)(row * 128 + u * 16));
            cpa16(wbase + soff, ((u < 4) ? Whi : Wlo) + row * 32 + wb + (u & 3), 16);
        }
    };

    stage_chunk(0, 0);
    CP_COMMIT();

    for (int ch = 0; ch < 8; ch++) {
        if (ch < 7) { stage_chunk(ch + 1, (ch + 1) & 1); CP_COMMIT(); cp_wait<1>(); }
        else        { cp_wait<0>(); }
        __syncthreads();

        uint32_t abase = sb + 1024 + (ch & 1) * 32768;
        uint32_t wbase = abase + 16384;
#pragma unroll
        for (int ks = 0; ks < 2; ks++) {
            int g = ks * 2 + lkg;
            uint32_t ahi[2][4], alo[2][4];
#pragma unroll
            for (int mt = 0; mt < 2; mt++) {
                uint32_t rb = (uint32_t)((wm + mt * 16 + lrow) * 128);
                ldsm4(ahi[mt], abase + SW128(rb + g * 16));
                ldsm4(alo[mt], abase + SW128(rb + (4 + g) * 16));
            }
#pragma unroll
            for (int nt2 = 0; nt2 < 4; nt2++) {
                uint32_t rb = (uint32_t)((wn + nt2 * 16 + lrow) * 128);
                uint32_t bh[4], bl[4];
                ldsm4(bh, wbase + SW128(rb + g * 16));
                ldsm4(bl, wbase + SW128(rb + (4 + g) * 16));
#pragma unroll
                for (int mt = 0; mt < 2; mt++) {
                    mma16816(acc[mt][nt2 * 2 + 0], ahi[mt], bh[0], bh[2]);
                    mma16816(acc[mt][nt2 * 2 + 1], ahi[mt], bh[1], bh[3]);
                    mma16816(acc[mt][nt2 * 2 + 0], ahi[mt], bl[0], bl[2]);
                    mma16816(acc[mt][nt2 * 2 + 1], ahi[mt], bl[1], bl[3]);
                    mma16816(acc[mt][nt2 * 2 + 0], alo[mt], bh[0], bh[2]);
                    mma16816(acc[mt][nt2 * 2 + 1], alo[mt], bh[1], bh[3]);
                }
            }
        }
        __syncthreads();
    }

    const float* bias_s = (const float*)smem;
    int r0 = lane >> 2;
    int cp = (lane & 3) * 2;
#pragma unroll
    for (int mt = 0; mt < 2; mt++) {
#pragma unroll
        for (int nt = 0; nt < 8; nt++) {
            int col = wn + nt * 8 + cp;
            float b0 = bias_s[col], b1 = bias_s[col + 1];
#pragma unroll
            for (int h = 0; h < 2; h++) {
                int rr = m0 + wm + mt * 16 + r0 + h * 8;
                if (rr >= M) continue;
                size_t base = (size_t)rr * 128 + col;
                float v0 = acc[mt][nt][h * 2 + 0] + b0;
                float v1 = acc[mt][nt][h * 2 + 1] + b1;
                if (PASS == 1) {
                    float2 rd = *(const float2*)(resid + base);
                    v0 += rd.x; v1 += rd.y;
                }
                *(float2*)(out + base) = make_float2(v0, v1);
                if (PASS == 0)
                    *(float2*)(g_g + base) = make_float2(elu1(v0), elu1(v1));
            }
        }
    }
}

// ---------------- launch ----------------
extern "C" void kernel_launch(void* const* d_in, const int* in_sizes, int n_in,
                              void* d_out, int out_size) {
    const int*   Di_rows  = (const int*)d_in[0];
    const int*   Di_cols  = (const int*)d_in[1];
    const float* Di_vals  = (const float*)d_in[2];
    const int*   DiA_rows = (const int*)d_in[3];
    const int*   DiA_cols = (const int*)d_in[4];
    const float* DiA_vals = (const float*)d_in[5];
    const float* v_in     = (const float*)d_in[6];
    const float* f_in     = (const float*)d_in[7];
    const float* bn0_g    = (const float*)d_in[8];
    const float* bn0_b    = (const float*)d_in[9];
    const float* fc0_w    = (const float*)d_in[10];
    const float* fc0_b    = (const float*)d_in[11];
    const float* bn1_g    = (const float*)d_in[12];
    const float* bn1_b    = (const float*)d_in[13];
    const float* fc1_w    = (const float*)d_in[14];
    const float* fc1_b    = (const float*)d_in[15];

    float* out_v = (float*)d_out;                 // v + v_out : [4,30000,128]
    float* out_f = out_v + SZ_V;                  // f_out     : [4,60000,128]

    const int T = 256;
    const int nv4 = (int)(SZ_V / 4);
    const int nf4 = (int)(SZ_F / 4);
    const int spGrid = (NNZk / 4 * 32) / T;       // 22500 blocks

    cudaFuncSetAttribute(gemm_mma_kernel<0>, cudaFuncAttributeMaxDynamicSharedMemorySize, SMEM_SZ);
    cudaFuncSetAttribute(gemm_mma_kernel<1>, cudaFuncAttributeMaxDynamicSharedMemorySize, SMEM_SZ);

    // 0) zero stats
    zero_stats_kernel<<<1, 256>>>();

    // 1) elu inputs + first-half BN stats + bf16 hi/lo emit
    elu_stats_kernel<0><<<1024, T>>>((const float4*)v_in, nv4);
    elu_stats_kernel<1><<<1024, T>>>((const float4*)f_in, nf4);

    // 2) spbmm1 per batch: zero slice immediately before its scatter (L2-warm pairing)
    for (int b = 0; b < BB; b++) {
        zero_slice_kernel<0><<<(FFd * 32 + T - 1) / T, T>>>(b);
        spbmm_kernel<0><<<spGrid, T>>>(Di_rows, Di_cols, Di_vals, b);
    }

    // 3) BN0 second-half stats + fold into fc0
    halfstats_kernel<0><<<1024, T>>>(nf4);
    finalize_fold_kernel<0><<<1, 256>>>(bn0_g, bn0_b, fc0_w, fc0_b, BB * FFd);

    // 4) gemm0: f_out (+ elu copy into g_g)
    gemm_mma_kernel<0><<<(BB * FFd + 127) / 128, 256, SMEM_SZ>>>(nullptr, out_f, BB * FFd);

    // 5) spbmm2 per batch
    for (int b = 0; b < BB; b++) {
        zero_slice_kernel<1><<<(NN * 32 + T - 1) / T, T>>>(b);
        spbmm_kernel<1><<<spGrid, T>>>(DiA_rows, DiA_cols, DiA_vals, b);
    }

    // 6) BN1 second-half stats + fold into fc1
    halfstats_kernel<1><<<1024, T>>>(nv4);
    finalize_fold_kernel<1><<<1, 256>>>(bn1_g, bn1_b, fc1_w, fc1_b, BB * NN);

    // 7) gemm1: out_v = v + linear(...)
    gemm_mma_kernel<1><<<(BB * NN + 127) / 128, 256, SMEM_SZ>>>(v_in, out_v, BB * NN);
}

// round 13
// speedup vs baseline: 1.0222x; 1.0222x over previous
#include <cuda_runtime.h>
#include <cuda_bf16.h>
#include <math.h>
#include <stdint.h>

// Problem constants
#define BB   4
#define NN   30000
#define FFd  60000
#define NNZk 720000

static const size_t SZ_V = (size_t)BB * NN * 128;   // 15,360,000
static const size_t SZ_F = (size_t)BB * FFd * 128;  // 30,720,000

// ---------------- scratch (static device arrays) ----------------
__device__ __nv_bfloat16 g_xinhi[15360000], g_xinlo[15360000];  // elu(v) bf16 hi/lo
__device__ __nv_bfloat16 g_finhi[30720000], g_finlo[30720000];  // elu(f) bf16 hi/lo
__device__ float  g_t0 [30720000];                    // spbmm1 out f32
__device__ __nv_bfloat16 g_t0hi[30720000], g_t0lo[30720000];
__device__ float  g_g  [30720000];                    // elu(f_out) f32 (spbmm2 src)
__device__ float  g_t1 [15360000];                    // spbmm2 out f32
__device__ __nv_bfloat16 g_t1hi[15360000], g_t1lo[15360000];
__device__ double g_stats0[512];
__device__ double g_stats1[512];
__device__ __nv_bfloat16 g_w0hi[32768], g_w0lo[32768];
__device__ __nv_bfloat16 g_w1hi[32768], g_w1lo[32768];
__device__ float  g_b0p[128];
__device__ float  g_b1p[128];

// ---------------- helpers ----------------
__device__ __forceinline__ uint32_t smem_u32(const void* p) {
    uint32_t a;
    asm("{ .reg .u64 t; cvta.to.shared.u64 t, %1; cvt.u32.u64 %0, t; }" : "=r"(a) : "l"(p));
    return a;
}

#define SW128(o) ((o) ^ (((o) >> 3) & 0x70))

__device__ __forceinline__ float elu1(float x) { return x > 0.f ? x : expm1f(x); }

__device__ __forceinline__ void ldsm4(uint32_t* d, uint32_t addr) {
    asm volatile("ldmatrix.sync.aligned.m8n8.x4.shared.b16 {%0,%1,%2,%3}, [%4];"
                 : "=r"(d[0]), "=r"(d[1]), "=r"(d[2]), "=r"(d[3]) : "r"(addr));
}

__device__ __forceinline__ void mma16816(float* c, const uint32_t* a, uint32_t b0, uint32_t b1) {
    asm volatile("mma.sync.aligned.m16n8k16.row.col.f32.bf16.bf16.f32 "
                 "{%0,%1,%2,%3}, {%4,%5,%6,%7}, {%8,%9}, {%0,%1,%2,%3};"
                 : "+f"(c[0]), "+f"(c[1]), "+f"(c[2]), "+f"(c[3])
                 : "r"(a[0]), "r"(a[1]), "r"(a[2]), "r"(a[3]), "r"(b0), "r"(b1));
}

__device__ __forceinline__ void cpa16(uint32_t smem, const uint4* gptr, int sz) {
    asm volatile("cp.async.cg.shared.global [%0], [%1], 16, %2;"
                 :: "r"(smem), "l"(gptr), "r"(sz) : "memory");
}
#define CP_COMMIT() asm volatile("cp.async.commit_group;" ::: "memory")
template <int N> __device__ __forceinline__ void cp_wait() {
    asm volatile("cp.async.wait_group %0;" :: "n"(N) : "memory");
}

__device__ __forceinline__ void split4_pack(float4 v, uint2& hi, uint2& lo) {
    __nv_bfloat16 h[4], l[4];
    h[0] = __float2bfloat16(v.x); l[0] = __float2bfloat16(v.x - __bfloat162float(h[0]));
    h[1] = __float2bfloat16(v.y); l[1] = __float2bfloat16(v.y - __bfloat162float(h[1]));
    h[2] = __float2bfloat16(v.z); l[2] = __float2bfloat16(v.z - __bfloat162float(h[2]));
    h[3] = __float2bfloat16(v.w); l[3] = __float2bfloat16(v.w - __bfloat162float(h[3]));
    hi = *(const uint2*)h; lo = *(const uint2*)l;
}

// ---------------- zero kernels ----------------
__global__ void zero_stats_kernel() {
    int i = threadIdx.x;
    ((double2*)g_stats0)[i] = make_double2(0.0, 0.0);
    ((double2*)g_stats1)[i] = make_double2(0.0, 0.0);
}

template <int WHICH>
__global__ void zero_slice_kernel(int batch) {
    int i = blockIdx.x * blockDim.x + threadIdx.x;
    int n4 = (WHICH == 0) ? FFd * 32 : NN * 32;
    if (i >= n4) return;
    float4* p = (WHICH == 0) ? ((float4*)g_t0 + (size_t)batch * (FFd * 32))
                             : ((float4*)g_t1 + (size_t)batch * (NN * 32));
    p[i] = make_float4(0.f, 0.f, 0.f, 0.f);
}

// ---------------- fused elu + column stats + bf16 hi/lo emit -----------------------
template <int WHICH>
__global__ void elu_stats_kernel(const float4* __restrict__ in, int n4) {
    __shared__ float rs[8][32][4], rq[8][32][4];
    double* stats = (WHICH == 0) ? g_stats1 : g_stats0;
    uint2* outhi = (uint2*)(WHICH == 0 ? g_xinhi : g_finhi);
    uint2* outlo = (uint2*)(WHICH == 0 ? g_xinlo : g_finlo);
    int tid = threadIdx.x;
    float s[4] = {0.f, 0.f, 0.f, 0.f}, q2[4] = {0.f, 0.f, 0.f, 0.f};
    for (int i = blockIdx.x * blockDim.x + tid; i < n4; i += gridDim.x * blockDim.x) {
        float4 v = in[i];
        v.x = elu1(v.x); v.y = elu1(v.y); v.z = elu1(v.z); v.w = elu1(v.w);
        uint2 hi, lo; split4_pack(v, hi, lo);
        outhi[i] = hi; outlo[i] = lo;
        s[0] += v.x; q2[0] += v.x * v.x;
        s[1] += v.y; q2[1] += v.y * v.y;
        s[2] += v.z; q2[2] += v.z * v.z;
        s[3] += v.w; q2[3] += v.w * v.w;
    }
    int cq = tid & 31, rt = tid >> 5;
#pragma unroll
    for (int e = 0; e < 4; e++) { rs[rt][cq][e] = s[e]; rq[rt][cq][e] = q2[e]; }
    __syncthreads();
    if (tid < 128) {
        int e = tid & 3, c = tid >> 2;
        float t = 0.f;
#pragma unroll
        for (int r = 0; r < 8; r++) t += rs[r][c][e];
        atomicAdd(&stats[c * 4 + e], (double)t);
    } else {
        int t2 = tid - 128;
        int e = t2 & 3, c = t2 >> 2;
        float t = 0.f;
#pragma unroll
        for (int r = 0; r < 8; r++) t += rq[r][c][e];
        atomicAdd(&stats[256 + c * 4 + e], (double)t);
    }
}

// ---- second-half stats over t0 / t1 + bf16 hi/lo emit ----
template <int PASS>
__global__ void halfstats_kernel(int n4) {
    __shared__ float rs[8][32][4], rq[8][32][4];
    const float4* src = (PASS == 0) ? (const float4*)g_t0 : (const float4*)g_t1;
    uint2* outhi = (uint2*)(PASS == 0 ? g_t0hi : g_t1hi);
    uint2* outlo = (uint2*)(PASS == 0 ? g_t0lo : g_t1lo);
    double* stats = (PASS == 0) ? g_stats0 : g_stats1;
    int tid = threadIdx.x;
    float s[4] = {0.f, 0.f, 0.f, 0.f}, q2[4] = {0.f, 0.f, 0.f, 0.f};
    for (int i = blockIdx.x * blockDim.x + tid; i < n4; i += gridDim.x * blockDim.x) {
        float4 v = src[i];
        uint2 hi, lo; split4_pack(v, hi, lo);
        outhi[i] = hi; outlo[i] = lo;
        s[0] += v.x; q2[0] += v.x * v.x;
        s[1] += v.y; q2[1] += v.y * v.y;
        s[2] += v.z; q2[2] += v.z * v.z;
        s[3] += v.w; q2[3] += v.w * v.w;
    }
    int cq = tid & 31, rt = tid >> 5;
#pragma unroll
    for (int e = 0; e < 4; e++) { rs[rt][cq][e] = s[e]; rq[rt][cq][e] = q2[e]; }
    __syncthreads();
    if (tid < 128) {
        int e = tid & 3, c = tid >> 2;
        float t = 0.f;
#pragma unroll
        for (int r = 0; r < 8; r++) t += rs[r][c][e];
        atomicAdd(&stats[128 + c * 4 + e], (double)t);
    } else {
        int t2 = tid - 128;
        int e = t2 & 3, c = t2 >> 2;
        float t = 0.f;
#pragma unroll
        for (int r = 0; r < 8; r++) t += rq[r][c][e];
        atomicAdd(&stats[384 + c * 4 + e], (double)t);
    }
}

// ---------------- sparse COO spmm, one batch per launch (L2-resident dst) ----------
// PASS0: src = g_xinhi + g_xinlo (reconstructed f32); PASS1: src = g_g f32.
template <int PASS>
__global__ void spbmm_kernel(const int* __restrict__ rows, const int* __restrict__ cols,
                             const float* __restrict__ vals, int batch) {
    int gw   = (blockIdx.x * blockDim.x + threadIdx.x) >> 5;
    int lane = threadIdx.x & 31;
    int e    = gw * 4 + (lane >> 3);
    int q    = lane & 7;
    if (e >= NNZk) return;
    int   r = rows[e];
    int   c = cols[e];
    float v = vals[e];
    float4 x;
    if (PASS == 0) {
        size_t off = (size_t)batch * NN * 128 + (size_t)c * 32 + q * 4;
        uint2 hr = *(const uint2*)(g_xinhi + off);
        uint2 lr = *(const uint2*)(g_xinlo + off);
        const __nv_bfloat16* h = (const __nv_bfloat16*)&hr;
        const __nv_bfloat16* l = (const __nv_bfloat16*)&lr;
        x.x = __bfloat162float(h[0]) + __bfloat162float(l[0]);
        x.y = __bfloat162float(h[1]) + __bfloat162float(l[1]);
        x.z = __bfloat162float(h[2]) + __bfloat162float(l[2]);
        x.w = __bfloat162float(h[3]) + __bfloat162float(l[3]);
    } else {
        const float* src = g_g + (size_t)batch * FFd * 128;
        x = *(const float4*)(src + (size_t)c * 32 + q * 4);
    }
    float*       dst = (PASS == 0) ? (g_t0 + (size_t)batch * FFd * 128)
                                   : (g_t1 + (size_t)batch * NN * 128);
    x.x *= v; x.y *= v; x.z *= v; x.w *= v;
    asm volatile("red.global.add.v4.f32 [%0], {%1, %2, %3, %4};"
                 :: "l"(dst + (size_t)r * 32 + q * 4), "f"(x.x), "f"(x.y), "f"(x.z), "f"(x.w)
                 : "memory");
}

// ---- finalize BN + fold into linear; emit bf16 hi/lo weights + fused bias ----
template <int PASS>
__global__ void finalize_fold_kernel(const float* __restrict__ gamma, const float* __restrict__ beta,
                                     const float* __restrict__ w, const float* __restrict__ bias,
                                     int M) {
    __shared__ float a_s[256], sh_s[256];
    const double* stats = (PASS == 0) ? g_stats0 : g_stats1;
    __nv_bfloat16* whi = (PASS == 0) ? g_w0hi : g_w1hi;
    __nv_bfloat16* wlo = (PASS == 0) ? g_w0lo : g_w1lo;
    float* bp = (PASS == 0) ? g_b0p : g_b1p;
    int j = threadIdx.x;
    double invM = 1.0 / (double)M;
    double mu   = stats[j] * invM;
    double var  = stats[256 + j] * invM - mu * mu;
    float a  = gamma[j] * rsqrtf((float)var + 1e-5f);
    float sh = beta[j] - (float)mu * a;
    a_s[j] = a; sh_s[j] = sh;
    __syncthreads();
    for (int idx = j; idx < 128 * 256; idx += 256) {
        float wv = w[idx] * a_s[idx & 255];
        __nv_bfloat16 hi = __float2bfloat16(wv);
        __nv_bfloat16 lo = __float2bfloat16(wv - __bfloat162float(hi));
        whi[idx] = hi; wlo[idx] = lo;
    }
    if (j < 128) {
        float s = bias[j];
        const float* wr = w + j * 256;
        for (int q = 0; q < 256; q++) s += sh_s[q] * wr[q];
        bp[j] = s;
    }
}

// ---------------- HMMA bf16 GEMM, cp.async double-buffered (all pre-split) ---------
// K chunks of 32; smem row = 128B [hi 64B | lo 64B], SW128-swizzled.
// stage s: A at 1024 + s*32768 (16KB), W at +16384 (16KB). 2 stages.
#define SMEM_SZ (1024 + 2 * 32768)   // 66560

template <int PASS>
__global__ void __launch_bounds__(256, 2)
gemm_mma_kernel(const float* __restrict__ resid, float* __restrict__ out, int M) {
    extern __shared__ char smem[];
    const uint4* A0hi = (const uint4*)(PASS == 0 ? g_finhi : g_xinhi);
    const uint4* A0lo = (const uint4*)(PASS == 0 ? g_finlo : g_xinlo);
    const uint4* A1hi = (const uint4*)(PASS == 0 ? g_t0hi : g_t1hi);
    const uint4* A1lo = (const uint4*)(PASS == 0 ? g_t0lo : g_t1lo);
    const uint4* Whi  = (const uint4*)(PASS == 0 ? g_w0hi : g_w1hi);
    const uint4* Wlo  = (const uint4*)(PASS == 0 ? g_w0lo : g_w1lo);
    const float* bp = (PASS == 0) ? g_b0p : g_b1p;

    uint32_t sb = smem_u32(smem);
    int tid  = threadIdx.x;
    int wid  = tid >> 5;
    int lane = tid & 31;
    int m0   = blockIdx.x * 128;
    int wm   = (wid & 3) * 32;
    int wn   = (wid >> 2) * 64;

    if (tid < 128) *(float*)(smem + tid * 4) = bp[tid];

    float acc[2][8][4];
#pragma unroll
    for (int mt = 0; mt < 2; mt++)
#pragma unroll
        for (int nt = 0; nt < 8; nt++)
#pragma unroll
            for (int e = 0; e < 4; e++) acc[mt][nt][e] = 0.f;

    int lrow = (lane & 7) + ((lane >> 3) & 1) * 8;
    int lkg  = lane >> 4;

    auto stage_chunk = [&](int ch, int s) {
        const uint4* Shi = (ch < 4) ? A0hi : A1hi;
        const uint4* Slo = (ch < 4) ? A0lo : A1lo;
        int cb = (ch & 3) * 4;
        int wb = ch * 4;
        uint32_t abase = sb + 1024 + s * 32768;
        uint32_t wbase = abase + 16384;
#pragma unroll
        for (int i = 0; i < 4; i++) {
            int idx = tid + i * 256;
            int row = idx >> 3;
            int u   = idx & 7;
            uint32_t soff = SW128((uint32_t)(row * 128 + u * 16));
            bool ok = (m0 + row < M);
            size_t gi = ok ? ((size_t)(m0 + row) * 16 + cb + (u & 3)) : 0;
            cpa16(abase + soff, ((u < 4) ? Shi : Slo) + gi, ok ? 16 : 0);
            cpa16(wbase + soff, ((u < 4) ? Whi : Wlo) + row * 32 + wb + (u & 3), 16);
        }
    };

    stage_chunk(0, 0);
    CP_COMMIT();

    for (int ch = 0; ch < 8; ch++) {
        if (ch < 7) { stage_chunk(ch + 1, (ch + 1) & 1); CP_COMMIT(); cp_wait<1>(); }
        else        { cp_wait<0>(); }
        __syncthreads();

        uint32_t abase = sb + 1024 + (ch & 1) * 32768;
        uint32_t wbase = abase + 16384;
#pragma unroll
        for (int ks = 0; ks < 2; ks++) {
            int g = ks * 2 + lkg;
            uint32_t ahi[2][4], alo[2][4];
#pragma unroll
            for (int mt = 0; mt < 2; mt++) {
                uint32_t rb = (uint32_t)((wm + mt * 16 + lrow) * 128);
                ldsm4(ahi[mt], abase + SW128(rb + g * 16));
                ldsm4(alo[mt], abase + SW128(rb + (4 + g) * 16));
            }
#pragma unroll
            for (int nt2 = 0; nt2 < 4; nt2++) {
                uint32_t rb = (uint32_t)((wn + nt2 * 16 + lrow) * 128);
                uint32_t bh[4], bl[4];
                ldsm4(bh, wbase + SW128(rb + g * 16));
                ldsm4(bl, wbase + SW128(rb + (4 + g) * 16));
#pragma unroll
                for (int mt = 0; mt < 2; mt++) {
                    mma16816(acc[mt][nt2 * 2 + 0], ahi[mt], bh[0], bh[2]);
                    mma16816(acc[mt][nt2 * 2 + 1], ahi[mt], bh[1], bh[3]);
                    mma16816(acc[mt][nt2 * 2 + 0], ahi[mt], bl[0], bl[2]);
                    mma16816(acc[mt][nt2 * 2 + 1], ahi[mt], bl[1], bl[3]);
                    mma16816(acc[mt][nt2 * 2 + 0], alo[mt], bh[0], bh[2]);
                    mma16816(acc[mt][nt2 * 2 + 1], alo[mt], bh[1], bh[3]);
                }
            }
        }
        __syncthreads();
    }

    const float* bias_s = (const float*)smem;
    int r0 = lane >> 2;
    int cp = (lane & 3) * 2;
#pragma unroll
    for (int mt = 0; mt < 2; mt++) {
#pragma unroll
        for (int nt = 0; nt < 8; nt++) {
            int col = wn + nt * 8 + cp;
            float b0 = bias_s[col], b1 = bias_s[col + 1];
#pragma unroll
            for (int h = 0; h < 2; h++) {
                int rr = m0 + wm + mt * 16 + r0 + h * 8;
                if (rr >= M) continue;
                size_t base = (size_t)rr * 128 + col;
                float v0 = acc[mt][nt][h * 2 + 0] + b0;
                float v1 = acc[mt][nt][h * 2 + 1] + b1;
                if (PASS == 1) {
                    float2 rd = *(const float2*)(resid + base);
                    v0 += rd.x; v1 += rd.y;
                }
                *(float2*)(out + base) = make_float2(v0, v1);
                if (PASS == 0)
                    *(float2*)(g_g + base) = make_float2(elu1(v0), elu1(v1));
            }
        }
    }
}

// ---------------- launch ----------------
extern "C" void kernel_launch(void* const* d_in, const int* in_sizes, int n_in,
                              void* d_out, int out_size) {
    const int*   Di_rows  = (const int*)d_in[0];
    const int*   Di_cols  = (const int*)d_in[1];
    const float* Di_vals  = (const float*)d_in[2];
    const int*   DiA_rows = (const int*)d_in[3];
    const int*   DiA_cols = (const int*)d_in[4];
    const float* DiA_vals = (const float*)d_in[5];
    const float* v_in     = (const float*)d_in[6];
    const float* f_in     = (const float*)d_in[7];
    const float* bn0_g    = (const float*)d_in[8];
    const float* bn0_b    = (const float*)d_in[9];
    const float* fc0_w    = (const float*)d_in[10];
    const float* fc0_b    = (const float*)d_in[11];
    const float* bn1_g    = (const float*)d_in[12];
    const float* bn1_b    = (const float*)d_in[13];
    const float* fc1_w    = (const float*)d_in[14];
    const float* fc1_b    = (const float*)d_in[15];

    float* out_v = (float*)d_out;                 // v + v_out : [4,30000,128]
    float* out_f = out_v + SZ_V;                  // f_out     : [4,60000,128]

    const int T = 256;
    const int nv4 = (int)(SZ_V / 4);
    const int nf4 = (int)(SZ_F / 4);
    const int spGrid = (NNZk / 4 * 32) / T;       // 22500 blocks

    cudaFuncSetAttribute(gemm_mma_kernel<0>, cudaFuncAttributeMaxDynamicSharedMemorySize, SMEM_SZ);
    cudaFuncSetAttribute(gemm_mma_kernel<1>, cudaFuncAttributeMaxDynamicSharedMemorySize, SMEM_SZ);

    // 0) zero stats
    zero_stats_kernel<<<1, 256>>>();

    // 1) elu inputs + first-half BN stats + bf16 hi/lo emit
    elu_stats_kernel<0><<<1024, T>>>((const float4*)v_in, nv4);
    elu_stats_kernel<1><<<1024, T>>>((const float4*)f_in, nf4);

    // 2) spbmm1 per batch: zero slice then scatter
    for (int b = 0; b < BB; b++) {
        zero_slice_kernel<0><<<(FFd * 32 + T - 1) / T, T>>>(b);
        spbmm_kernel<0><<<spGrid, T>>>(Di_rows, Di_cols, Di_vals, b);
    }

    // 3) BN0 second-half stats + t0 hi/lo + fold into fc0
    halfstats_kernel<0><<<1024, T>>>(nf4);
    finalize_fold_kernel<0><<<1, 256>>>(bn0_g, bn0_b, fc0_w, fc0_b, BB * FFd);

    // 4) gemm0: f_out (+ elu copy into g_g)
    gemm_mma_kernel<0><<<(BB * FFd + 127) / 128, 256, SMEM_SZ>>>(nullptr, out_f, BB * FFd);

    // 5) spbmm2 per batch
    for (int b = 0; b < BB; b++) {
        zero_slice_kernel<1><<<(NN * 32 + T - 1) / T, T>>>(b);
        spbmm_kernel<1><<<spGrid, T>>>(DiA_rows, DiA_cols, DiA_vals, b);
    }

    // 6) BN1 second-half stats + t1 hi/lo + fold into fc1
    halfstats_kernel<1><<<1024, T>>>(nv4);
    finalize_fold_kernel<1><<<1, 256>>>(bn1_g, bn1_b, fc1_w, fc1_b, BB * NN);

    // 7) gemm1: out_v = v + linear(...)
    gemm_mma_kernel<1><<<(BB * NN + 127) / 128, 256, SMEM_SZ>>>(v_in, out_v, BB * NN);
}

// round 15
// speedup vs baseline: 1.0248x; 1.0026x over previous
#include <cuda_runtime.h>
#include <cuda_bf16.h>
#include <math.h>
#include <stdint.h>

// Problem constants
#define BB   4
#define NN   30000
#define FFd  60000
#define NNZk 720000

static const size_t SZ_V = (size_t)BB * NN * 128;   // 15,360,000
static const size_t SZ_F = (size_t)BB * FFd * 128;  // 30,720,000

// ---------------- scratch (static device arrays) ----------------
__device__ __nv_bfloat16 g_xinhi[15360000], g_xinlo[15360000];  // elu(v) bf16 hi/lo
__device__ __nv_bfloat16 g_finhi[30720000], g_finlo[30720000];  // elu(f) bf16 hi/lo
__device__ float  g_t0 [30720000];                    // spbmm1 out f32
__device__ __nv_bfloat16 g_t0hi[30720000], g_t0lo[30720000];
__device__ float  g_g  [30720000];                    // elu(f_out) f32 (spbmm2 src)
__device__ float  g_t1 [15360000];                    // spbmm2 out f32
__device__ __nv_bfloat16 g_t1hi[15360000], g_t1lo[15360000];
__device__ double g_stats0[512];
__device__ double g_stats1[512];
__device__ __nv_bfloat16 g_w0hi[32768], g_w0lo[32768];
__device__ __nv_bfloat16 g_w1hi[32768], g_w1lo[32768];
__device__ float  g_b0p[128];
__device__ float  g_b1p[128];

// ---------------- helpers ----------------
__device__ __forceinline__ uint32_t smem_u32(const void* p) {
    uint32_t a;
    asm("{ .reg .u64 t; cvta.to.shared.u64 t, %1; cvt.u32.u64 %0, t; }" : "=r"(a) : "l"(p));
    return a;
}

#define SW128(o) ((o) ^ (((o) >> 3) & 0x70))

__device__ __forceinline__ float elu1(float x) { return x > 0.f ? x : expm1f(x); }

__device__ __forceinline__ void ldsm4(uint32_t* d, uint32_t addr) {
    asm volatile("ldmatrix.sync.aligned.m8n8.x4.shared.b16 {%0,%1,%2,%3}, [%4];"
                 : "=r"(d[0]), "=r"(d[1]), "=r"(d[2]), "=r"(d[3]) : "r"(addr));
}

__device__ __forceinline__ void mma16816(float* c, const uint32_t* a, uint32_t b0, uint32_t b1) {
    asm volatile("mma.sync.aligned.m16n8k16.row.col.f32.bf16.bf16.f32 "
                 "{%0,%1,%2,%3}, {%4,%5,%6,%7}, {%8,%9}, {%0,%1,%2,%3};"
                 : "+f"(c[0]), "+f"(c[1]), "+f"(c[2]), "+f"(c[3])
                 : "r"(a[0]), "r"(a[1]), "r"(a[2]), "r"(a[3]), "r"(b0), "r"(b1));
}

__device__ __forceinline__ void cpa16(uint32_t smem, const uint4* gptr, int sz) {
    asm volatile("cp.async.cg.shared.global [%0], [%1], 16, %2;"
                 :: "r"(smem), "l"(gptr), "r"(sz) : "memory");
}
#define CP_COMMIT() asm volatile("cp.async.commit_group;" ::: "memory")
template <int N> __device__ __forceinline__ void cp_wait() {
    asm volatile("cp.async.wait_group %0;" :: "n"(N) : "memory");
}

__device__ __forceinline__ void split4_pack(float4 v, uint2& hi, uint2& lo) {
    __nv_bfloat16 h[4], l[4];
    h[0] = __float2bfloat16(v.x); l[0] = __float2bfloat16(v.x - __bfloat162float(h[0]));
    h[1] = __float2bfloat16(v.y); l[1] = __float2bfloat16(v.y - __bfloat162float(h[1]));
    h[2] = __float2bfloat16(v.z); l[2] = __float2bfloat16(v.z - __bfloat162float(h[2]));
    h[3] = __float2bfloat16(v.w); l[3] = __float2bfloat16(v.w - __bfloat162float(h[3]));
    hi = *(const uint2*)h; lo = *(const uint2*)l;
}

// ---------------- zero kernels ----------------
__global__ void zero_stats_kernel() {
    int i = threadIdx.x;
    ((double2*)g_stats0)[i] = make_double2(0.0, 0.0);
    ((double2*)g_stats1)[i] = make_double2(0.0, 0.0);
}

template <int WHICH>
__global__ void zero_slice_kernel(int batch) {
    int i = blockIdx.x * blockDim.x + threadIdx.x;
    int n4 = (WHICH == 0) ? FFd * 32 : NN * 32;
    if (i >= n4) return;
    float4* p = (WHICH == 0) ? ((float4*)g_t0 + (size_t)batch * (FFd * 32))
                             : ((float4*)g_t1 + (size_t)batch * (NN * 32));
    p[i] = make_float4(0.f, 0.f, 0.f, 0.f);
}

// ---------------- fused elu + column stats + bf16 hi/lo emit -----------------------
template <int WHICH>
__global__ void elu_stats_kernel(const float4* __restrict__ in, int n4) {
    __shared__ float rs[8][32][4], rq[8][32][4];
    double* stats = (WHICH == 0) ? g_stats1 : g_stats0;
    uint2* outhi = (uint2*)(WHICH == 0 ? g_xinhi : g_finhi);
    uint2* outlo = (uint2*)(WHICH == 0 ? g_xinlo : g_finlo);
    int tid = threadIdx.x;
    float s[4] = {0.f, 0.f, 0.f, 0.f}, q2[4] = {0.f, 0.f, 0.f, 0.f};
    for (int i = blockIdx.x * blockDim.x + tid; i < n4; i += gridDim.x * blockDim.x) {
        float4 v = in[i];
        v.x = elu1(v.x); v.y = elu1(v.y); v.z = elu1(v.z); v.w = elu1(v.w);
        uint2 hi, lo; split4_pack(v, hi, lo);
        outhi[i] = hi; outlo[i] = lo;
        s[0] += v.x; q2[0] += v.x * v.x;
        s[1] += v.y; q2[1] += v.y * v.y;
        s[2] += v.z; q2[2] += v.z * v.z;
        s[3] += v.w; q2[3] += v.w * v.w;
    }
    int cq = tid & 31, rt = tid >> 5;
#pragma unroll
    for (int e = 0; e < 4; e++) { rs[rt][cq][e] = s[e]; rq[rt][cq][e] = q2[e]; }
    __syncthreads();
    if (tid < 128) {
        int e = tid & 3, c = tid >> 2;
        float t = 0.f;
#pragma unroll
        for (int r = 0; r < 8; r++) t += rs[r][c][e];
        atomicAdd(&stats[c * 4 + e], (double)t);
    } else {
        int t2 = tid - 128;
        int e = t2 & 3, c = t2 >> 2;
        float t = 0.f;
#pragma unroll
        for (int r = 0; r < 8; r++) t += rq[r][c][e];
        atomicAdd(&stats[256 + c * 4 + e], (double)t);
    }
}

// ---- second-half stats over t0 / t1 + bf16 hi/lo emit ----
template <int PASS>
__global__ void halfstats_kernel(int n4) {
    __shared__ float rs[8][32][4], rq[8][32][4];
    const float4* src = (PASS == 0) ? (const float4*)g_t0 : (const float4*)g_t1;
    uint2* outhi = (uint2*)(PASS == 0 ? g_t0hi : g_t1hi);
    uint2* outlo = (uint2*)(PASS == 0 ? g_t0lo : g_t1lo);
    double* stats = (PASS == 0) ? g_stats0 : g_stats1;
    int tid = threadIdx.x;
    float s[4] = {0.f, 0.f, 0.f, 0.f}, q2[4] = {0.f, 0.f, 0.f, 0.f};
    for (int i = blockIdx.x * blockDim.x + tid; i < n4; i += gridDim.x * blockDim.x) {
        float4 v = src[i];
        uint2 hi, lo; split4_pack(v, hi, lo);
        outhi[i] = hi; outlo[i] = lo;
        s[0] += v.x; q2[0] += v.x * v.x;
        s[1] += v.y; q2[1] += v.y * v.y;
        s[2] += v.z; q2[2] += v.z * v.z;
        s[3] += v.w; q2[3] += v.w * v.w;
    }
    int cq = tid & 31, rt = tid >> 5;
#pragma unroll
    for (int e = 0; e < 4; e++) { rs[rt][cq][e] = s[e]; rq[rt][cq][e] = q2[e]; }
    __syncthreads();
    if (tid < 128) {
        int e = tid & 3, c = tid >> 2;
        float t = 0.f;
#pragma unroll
        for (int r = 0; r < 8; r++) t += rs[r][c][e];
        atomicAdd(&stats[128 + c * 4 + e], (double)t);
    } else {
        int t2 = tid - 128;
        int e = t2 & 3, c = t2 >> 2;
        float t = 0.f;
#pragma unroll
        for (int r = 0; r < 8; r++) t += rq[r][c][e];
        atomicAdd(&stats[384 + c * 4 + e], (double)t);
    }
}

// ---------------- sparse COO spmm, one batch per launch (L2-resident dst) ----------
// PASS0: src = g_xinhi + g_xinlo (reconstructed f32); PASS1: src = g_g f32.
template <int PASS>
__global__ void spbmm_kernel(const int* __restrict__ rows, const int* __restrict__ cols,
                             const float* __restrict__ vals, int batch) {
    int gw   = (blockIdx.x * blockDim.x + threadIdx.x) >> 5;
    int lane = threadIdx.x & 31;
    int e    = gw * 4 + (lane >> 3);
    int q    = lane & 7;
    if (e >= NNZk) return;
    int   r = rows[e];
    int   c = cols[e];
    float v = vals[e];
    float4 x;
    if (PASS == 0) {
        size_t off = (size_t)batch * NN * 128 + (size_t)c * 32 + q * 4;
        uint2 hr = *(const uint2*)(g_xinhi + off);
        uint2 lr = *(const uint2*)(g_xinlo + off);
        const __nv_bfloat16* h = (const __nv_bfloat16*)&hr;
        const __nv_bfloat16* l = (const __nv_bfloat16*)&lr;
        x.x = __bfloat162float(h[0]) + __bfloat162float(l[0]);
        x.y = __bfloat162float(h[1]) + __bfloat162float(l[1]);
        x.z = __bfloat162float(h[2]) + __bfloat162float(l[2]);
        x.w = __bfloat162float(h[3]) + __bfloat162float(l[3]);
    } else {
        const float* src = g_g + (size_t)batch * FFd * 128;
        x = *(const float4*)(src + (size_t)c * 32 + q * 4);
    }
    float*       dst = (PASS == 0) ? (g_t0 + (size_t)batch * FFd * 128)
                                   : (g_t1 + (size_t)batch * NN * 128);
    x.x *= v; x.y *= v; x.z *= v; x.w *= v;
    asm volatile("red.global.add.v4.f32 [%0], {%1, %2, %3, %4};"
                 :: "l"(dst + (size_t)r * 32 + q * 4), "f"(x.x), "f"(x.y), "f"(x.z), "f"(x.w)
                 : "memory");
}

// ---- finalize BN + fold into linear; emit bf16 hi/lo weights + fused bias ----
template <int PASS>
__global__ void finalize_fold_kernel(const float* __restrict__ gamma, const float* __restrict__ beta,
                                     const float* __restrict__ w, const float* __restrict__ bias,
                                     int M) {
    __shared__ float a_s[256], sh_s[256];
    const double* stats = (PASS == 0) ? g_stats0 : g_stats1;
    __nv_bfloat16* whi = (PASS == 0) ? g_w0hi : g_w1hi;
    __nv_bfloat16* wlo = (PASS == 0) ? g_w0lo : g_w1lo;
    float* bp = (PASS == 0) ? g_b0p : g_b1p;
    int j = threadIdx.x;
    double invM = 1.0 / (double)M;
    double mu   = stats[j] * invM;
    double var  = stats[256 + j] * invM - mu * mu;
    float a  = gamma[j] * rsqrtf((float)var + 1e-5f);
    float sh = beta[j] - (float)mu * a;
    a_s[j] = a; sh_s[j] = sh;
    __syncthreads();
    for (int idx = j; idx < 128 * 256; idx += 256) {
        float wv = w[idx] * a_s[idx & 255];
        __nv_bfloat16 hi = __float2bfloat16(wv);
        __nv_bfloat16 lo = __float2bfloat16(wv - __bfloat162float(hi));
        whi[idx] = hi; wlo[idx] = lo;
    }
    if (j < 128) {
        float s = bias[j];
        const float* wr = w + j * 256;
        for (int q = 0; q < 256; q++) s += sh_s[q] * wr[q];
        bp[j] = s;
    }
}

// ---------------- HMMA bf16 GEMM, cp.async double-buffered (all pre-split) ---------
// K chunks of 32; smem row = 128B [hi 64B | lo 64B], SW128-swizzled.
// stage s: A at 1024 + s*32768 (16KB), W at +16384 (16KB). 2 stages.
#define SMEM_SZ (1024 + 2 * 32768)   // 66560

template <int PASS>
__global__ void __launch_bounds__(256, 2)
gemm_mma_kernel(const float* __restrict__ resid, float* __restrict__ out, int M) {
    extern __shared__ char smem[];
    const uint4* A0hi = (const uint4*)(PASS == 0 ? g_finhi : g_xinhi);
    const uint4* A0lo = (const uint4*)(PASS == 0 ? g_finlo : g_xinlo);
    const uint4* A1hi = (const uint4*)(PASS == 0 ? g_t0hi : g_t1hi);
    const uint4* A1lo = (const uint4*)(PASS == 0 ? g_t0lo : g_t1lo);
    const uint4* Whi  = (const uint4*)(PASS == 0 ? g_w0hi : g_w1hi);
    const uint4* Wlo  = (const uint4*)(PASS == 0 ? g_w0lo : g_w1lo);
    const float* bp = (PASS == 0) ? g_b0p : g_b1p;

    uint32_t sb = smem_u32(smem);
    int tid  = threadIdx.x;
    int wid  = tid >> 5;
    int lane = tid & 31;
    int m0   = blockIdx.x * 128;
    int wm   = (wid & 3) * 32;
    int wn   = (wid >> 2) * 64;

    if (tid < 128) *(float*)(smem + tid * 4) = bp[tid];

    float acc[2][8][4];
#pragma unroll
    for (int mt = 0; mt < 2; mt++)
#pragma unroll
        for (int nt = 0; nt < 8; nt++)
#pragma unroll
            for (int e = 0; e < 4; e++) acc[mt][nt][e] = 0.f;

    int lrow = (lane & 7) + ((lane >> 3) & 1) * 8;
    int lkg  = lane >> 4;

    auto stage_chunk = [&](int ch, int s) {
        const uint4* Shi = (ch < 4) ? A0hi : A1hi;
        const uint4* Slo = (ch < 4) ? A0lo : A1lo;
        int cb = (ch & 3) * 4;
        int wb = ch * 4;
        uint32_t abase = sb + 1024 + s * 32768;
        uint32_t wbase = abase + 16384;
#pragma unroll
        for (int i = 0; i < 4; i++) {
            int idx = tid + i * 256;
            int row = idx >> 3;
            int u   = idx & 7;
            uint32_t soff = SW128((uint32_t)(row * 128 + u * 16));
            bool ok = (m0 + row < M);
            size_t gi = ok ? ((size_t)(m0 + row) * 16 + cb + (u & 3)) : 0;
            cpa16(abase + soff, ((u < 4) ? Shi : Slo) + gi, ok ? 16 : 0);
            cpa16(wbase + soff, ((u < 4) ? Whi : Wlo) + row * 32 + wb + (u & 3), 16);
        }
    };

    stage_chunk(0, 0);
    CP_COMMIT();

    for (int ch = 0; ch < 8; ch++) {
        if (ch < 7) { stage_chunk(ch + 1, (ch + 1) & 1); CP_COMMIT(); cp_wait<1>(); }
        else        { cp_wait<0>(); }
        __syncthreads();

        uint32_t abase = sb + 1024 + (ch & 1) * 32768;
        uint32_t wbase = abase + 16384;
#pragma unroll
        for (int ks = 0; ks < 2; ks++) {
            int g = ks * 2 + lkg;
            uint32_t ahi[2][4], alo[2][4];
#pragma unroll
            for (int mt = 0; mt < 2; mt++) {
                uint32_t rb = (uint32_t)((wm + mt * 16 + lrow) * 128);
                ldsm4(ahi[mt], abase + SW128(rb + g * 16));
                ldsm4(alo[mt], abase + SW128(rb + (4 + g) * 16));
            }
#pragma unroll
            for (int nt2 = 0; nt2 < 4; nt2++) {
                uint32_t rb = (uint32_t)((wn + nt2 * 16 + lrow) * 128);
                uint32_t bh[4], bl[4];
                ldsm4(bh, wbase + SW128(rb + g * 16));
                ldsm4(bl, wbase + SW128(rb + (4 + g) * 16));
#pragma unroll
                for (int mt = 0; mt < 2; mt++) {
                    mma16816(acc[mt][nt2 * 2 + 0], ahi[mt], bh[0], bh[2]);
                    mma16816(acc[mt][nt2 * 2 + 1], ahi[mt], bh[1], bh[3]);
                    mma16816(acc[mt][nt2 * 2 + 0], ahi[mt], bl[0], bl[2]);
                    mma16816(acc[mt][nt2 * 2 + 1], ahi[mt], bl[1], bl[3]);
                    mma16816(acc[mt][nt2 * 2 + 0], alo[mt], bh[0], bh[2]);
                    mma16816(acc[mt][nt2 * 2 + 1], alo[mt], bh[1], bh[3]);
                }
            }
        }
        __syncthreads();
    }

    const float* bias_s = (const float*)smem;
    int r0 = lane >> 2;
    int cp = (lane & 3) * 2;
#pragma unroll
    for (int mt = 0; mt < 2; mt++) {
#pragma unroll
        for (int nt = 0; nt < 8; nt++) {
            int col = wn + nt * 8 + cp;
            float b0 = bias_s[col], b1 = bias_s[col + 1];
#pragma unroll
            for (int h = 0; h < 2; h++) {
                int rr = m0 + wm + mt * 16 + r0 + h * 8;
                if (rr >= M) continue;
                size_t base = (size_t)rr * 128 + col;
                float v0 = acc[mt][nt][h * 2 + 0] + b0;
                float v1 = acc[mt][nt][h * 2 + 1] + b1;
                if (PASS == 1) {
                    float2 rd = *(const float2*)(resid + base);
                    v0 += rd.x; v1 += rd.y;
                }
                *(float2*)(out + base) = make_float2(v0, v1);
                if (PASS == 0)
                    *(float2*)(g_g + base) = make_float2(elu1(v0), elu1(v1));
            }
        }
    }
}

// ---------------- launch ----------------
extern "C" void kernel_launch(void* const* d_in, const int* in_sizes, int n_in,
                              void* d_out, int out_size) {
    const int*   Di_rows  = (const int*)d_in[0];
    const int*   Di_cols  = (const int*)d_in[1];
    const float* Di_vals  = (const float*)d_in[2];
    const int*   DiA_rows = (const int*)d_in[3];
    const int*   DiA_cols = (const int*)d_in[4];
    const float* DiA_vals = (const float*)d_in[5];
    const float* v_in     = (const float*)d_in[6];
    const float* f_in     = (const float*)d_in[7];
    const float* bn0_g    = (const float*)d_in[8];
    const float* bn0_b    = (const float*)d_in[9];
    const float* fc0_w    = (const float*)d_in[10];
    const float* fc0_b    = (const float*)d_in[11];
    const float* bn1_g    = (const float*)d_in[12];
    const float* bn1_b    = (const float*)d_in[13];
    const float* fc1_w    = (const float*)d_in[14];
    const float* fc1_b    = (const float*)d_in[15];

    float* out_v = (float*)d_out;                 // v + v_out : [4,30000,128]
    float* out_f = out_v + SZ_V;                  // f_out     : [4,60000,128]

    const int T = 256;
    const int nv4 = (int)(SZ_V / 4);
    const int nf4 = (int)(SZ_F / 4);
    const int spGrid = (NNZk / 4 * 32) / T;       // 22500 blocks

    cudaFuncSetAttribute(gemm_mma_kernel<0>, cudaFuncAttributeMaxDynamicSharedMemorySize, SMEM_SZ);
    cudaFuncSetAttribute(gemm_mma_kernel<1>, cudaFuncAttributeMaxDynamicSharedMemorySize, SMEM_SZ);

    // 0) zero stats
    zero_stats_kernel<<<1, 256>>>();

    // 1) elu inputs + first-half BN stats + bf16 hi/lo emit
    elu_stats_kernel<0><<<1024, T>>>((const float4*)v_in, nv4);
    elu_stats_kernel<1><<<1024, T>>>((const float4*)f_in, nf4);

    // 2) spbmm1 per batch: zero slice then scatter
    for (int b = 0; b < BB; b++) {
        zero_slice_kernel<0><<<(FFd * 32 + T - 1) / T, T>>>(b);
        spbmm_kernel<0><<<spGrid, T>>>(Di_rows, Di_cols, Di_vals, b);
    }

    // 3) BN0 second-half stats + t0 hi/lo + fold into fc0
    halfstats_kernel<0><<<1024, T>>>(nf4);
    finalize_fold_kernel<0><<<1, 256>>>(bn0_g, bn0_b, fc0_w, fc0_b, BB * FFd);

    // 4) gemm0: f_out (+ elu copy into g_g)
    gemm_mma_kernel<0><<<(BB * FFd + 127) / 128, 256, SMEM_SZ>>>(nullptr, out_f, BB * FFd);

    // 5) spbmm2 per batch
    for (int b = 0; b < BB; b++) {
        zero_slice_kernel<1><<<(NN * 32 + T - 1) / T, T>>>(b);
        spbmm_kernel<1><<<spGrid, T>>>(DiA_rows, DiA_cols, DiA_vals, b);
    }

    // 6) BN1 second-half stats + t1 hi/lo + fold into fc1
    halfstats_kernel<1><<<1024, T>>>(nv4);
    finalize_fold_kernel<1><<<1, 256>>>(bn1_g, bn1_b, fc1_w, fc1_b, BB * NN);

    // 7) gemm1: out_v = v + linear(...)
    gemm_mma_kernel<1><<<(BB * NN + 127) / 128, 256, SMEM_SZ>>>(v_in, out_v, BB * NN);
}

// round 16
// speedup vs baseline: 1.1997x; 1.1707x over previous
#include <cuda_runtime.h>
#include <cuda_fp16.h>
#include <math.h>
#include <stdint.h>

// Problem constants
#define BB   4
#define NN   30000
#define FFd  60000
#define NNZk 720000

static const size_t SZ_V = (size_t)BB * NN * 128;   // 15,360,000
static const size_t SZ_F = (size_t)BB * FFd * 128;  // 30,720,000

// ---------------- scratch (static device arrays) ----------------
__device__ __half g_xinh[15360000];                   // elu(v) fp16
__device__ __half g_finh[30720000];                   // elu(f) fp16
__device__ float  g_t0 [30720000];                    // spbmm1 out f32
__device__ __half g_t0h[30720000];                    // t0 fp16
__device__ __half g_g  [30720000];                    // elu(f_out) fp16 (spbmm2 src)
__device__ float  g_t1 [15360000];                    // spbmm2 out f32
__device__ __half g_t1h[15360000];                    // t1 fp16
__device__ double g_stats0[512];
__device__ double g_stats1[512];
__device__ __half g_w0hi[32768], g_w0lo[32768];       // BN-folded fc0 weight fp16 hi/lo
__device__ __half g_w1hi[32768], g_w1lo[32768];
__device__ float  g_b0p[128];
__device__ float  g_b1p[128];

// ---------------- helpers ----------------
__device__ __forceinline__ uint32_t smem_u32(const void* p) {
    uint32_t a;
    asm("{ .reg .u64 t; cvta.to.shared.u64 t, %1; cvt.u32.u64 %0, t; }" : "=r"(a) : "l"(p));
    return a;
}

#define SW128(o) ((o) ^ (((o) >> 3) & 0x70))

__device__ __forceinline__ float elu1(float x) { return x > 0.f ? x : expm1f(x); }

__device__ __forceinline__ void ldsm4(uint32_t* d, uint32_t addr) {
    asm volatile("ldmatrix.sync.aligned.m8n8.x4.shared.b16 {%0,%1,%2,%3}, [%4];"
                 : "=r"(d[0]), "=r"(d[1]), "=r"(d[2]), "=r"(d[3]) : "r"(addr));
}

__device__ __forceinline__ void mma16816h(float* c, const uint32_t* a, uint32_t b0, uint32_t b1) {
    asm volatile("mma.sync.aligned.m16n8k16.row.col.f32.f16.f16.f32 "
                 "{%0,%1,%2,%3}, {%4,%5,%6,%7}, {%8,%9}, {%0,%1,%2,%3};"
                 : "+f"(c[0]), "+f"(c[1]), "+f"(c[2]), "+f"(c[3])
                 : "r"(a[0]), "r"(a[1]), "r"(a[2]), "r"(a[3]), "r"(b0), "r"(b1));
}

__device__ __forceinline__ void cpa16(uint32_t smem, const uint4* gptr, int sz) {
    asm volatile("cp.async.cg.shared.global [%0], [%1], 16, %2;"
                 :: "r"(smem), "l"(gptr), "r"(sz) : "memory");
}
#define CP_COMMIT() asm volatile("cp.async.commit_group;" ::: "memory")
template <int N> __device__ __forceinline__ void cp_wait() {
    asm volatile("cp.async.wait_group %0;" :: "n"(N) : "memory");
}

// pack 4 floats -> 4 fp16 (uint2)
__device__ __forceinline__ uint2 pack_h4(float4 v) {
    __half2 a = __float22half2_rn(make_float2(v.x, v.y));
    __half2 b = __float22half2_rn(make_float2(v.z, v.w));
    uint2 r;
    r.x = *(uint32_t*)&a;
    r.y = *(uint32_t*)&b;
    return r;
}

// ---------------- zero kernels ----------------
__global__ void zero_stats_kernel() {
    int i = threadIdx.x;
    ((double2*)g_stats0)[i] = make_double2(0.0, 0.0);
    ((double2*)g_stats1)[i] = make_double2(0.0, 0.0);
}

template <int WHICH>
__global__ void zero_slice_kernel(int batch) {
    int i = blockIdx.x * blockDim.x + threadIdx.x;
    int n4 = (WHICH == 0) ? FFd * 32 : NN * 32;
    if (i >= n4) return;
    float4* p = (WHICH == 0) ? ((float4*)g_t0 + (size_t)batch * (FFd * 32))
                             : ((float4*)g_t1 + (size_t)batch * (NN * 32));
    p[i] = make_float4(0.f, 0.f, 0.f, 0.f);
}

// ---------------- fused elu + column stats + fp16 emit -----------------------------
// WHICH==0: v -> g_xinh, stats1 cols [0..127];  WHICH==1: f -> g_finh, stats0 cols [0..127]
template <int WHICH>
__global__ void elu_stats_kernel(const float4* __restrict__ in, int n4) {
    __shared__ float rs[8][32][4], rq[8][32][4];
    double* stats = (WHICH == 0) ? g_stats1 : g_stats0;
    uint2* outh = (uint2*)(WHICH == 0 ? g_xinh : g_finh);
    int tid = threadIdx.x;
    float s[4] = {0.f, 0.f, 0.f, 0.f}, q2[4] = {0.f, 0.f, 0.f, 0.f};
    for (int i = blockIdx.x * blockDim.x + tid; i < n4; i += gridDim.x * blockDim.x) {
        float4 v = in[i];
        v.x = elu1(v.x); v.y = elu1(v.y); v.z = elu1(v.z); v.w = elu1(v.w);
        outh[i] = pack_h4(v);
        s[0] += v.x; q2[0] += v.x * v.x;
        s[1] += v.y; q2[1] += v.y * v.y;
        s[2] += v.z; q2[2] += v.z * v.z;
        s[3] += v.w; q2[3] += v.w * v.w;
    }
    int cq = tid & 31, rt = tid >> 5;
#pragma unroll
    for (int e = 0; e < 4; e++) { rs[rt][cq][e] = s[e]; rq[rt][cq][e] = q2[e]; }
    __syncthreads();
    if (tid < 128) {
        int e = tid & 3, c = tid >> 2;
        float t = 0.f;
#pragma unroll
        for (int r = 0; r < 8; r++) t += rs[r][c][e];
        atomicAdd(&stats[c * 4 + e], (double)t);
    } else {
        int t2 = tid - 128;
        int e = t2 & 3, c = t2 >> 2;
        float t = 0.f;
#pragma unroll
        for (int r = 0; r < 8; r++) t += rq[r][c][e];
        atomicAdd(&stats[256 + c * 4 + e], (double)t);
    }
}

// ---- second-half stats over t0 / t1 + fp16 emit ----
template <int PASS>
__global__ void halfstats_kernel(int n4) {
    __shared__ float rs[8][32][4], rq[8][32][4];
    const float4* src = (PASS == 0) ? (const float4*)g_t0 : (const float4*)g_t1;
    uint2* outh = (uint2*)(PASS == 0 ? g_t0h : g_t1h);
    double* stats = (PASS == 0) ? g_stats0 : g_stats1;
    int tid = threadIdx.x;
    float s[4] = {0.f, 0.f, 0.f, 0.f}, q2[4] = {0.f, 0.f, 0.f, 0.f};
    for (int i = blockIdx.x * blockDim.x + tid; i < n4; i += gridDim.x * blockDim.x) {
        float4 v = src[i];
        outh[i] = pack_h4(v);
        s[0] += v.x; q2[0] += v.x * v.x;
        s[1] += v.y; q2[1] += v.y * v.y;
        s[2] += v.z; q2[2] += v.z * v.z;
        s[3] += v.w; q2[3] += v.w * v.w;
    }
    int cq = tid & 31, rt = tid >> 5;
#pragma unroll
    for (int e = 0; e < 4; e++) { rs[rt][cq][e] = s[e]; rq[rt][cq][e] = q2[e]; }
    __syncthreads();
    if (tid < 128) {
        int e = tid & 3, c = tid >> 2;
        float t = 0.f;
#pragma unroll
        for (int r = 0; r < 8; r++) t += rs[r][c][e];
        atomicAdd(&stats[128 + c * 4 + e], (double)t);
    } else {
        int t2 = tid - 128;
        int e = t2 & 3, c = t2 >> 2;
        float t = 0.f;
#pragma unroll
        for (int r = 0; r < 8; r++) t += rq[r][c][e];
        atomicAdd(&stats[384 + c * 4 + e], (double)t);
    }
}

// ---------------- sparse COO spmm, one batch per launch (L2-resident dst) ----------
// PASS0: src = g_xinh (fp16); PASS1: src = g_g (fp16).
template <int PASS>
__global__ void spbmm_kernel(const int* __restrict__ rows, const int* __restrict__ cols,
                             const float* __restrict__ vals, int batch) {
    int gw   = (blockIdx.x * blockDim.x + threadIdx.x) >> 5;
    int lane = threadIdx.x & 31;
    int e    = gw * 4 + (lane >> 3);
    int q    = lane & 7;
    if (e >= NNZk) return;
    int   r = rows[e];
    int   c = cols[e];
    float v = vals[e];
    const __half* srcb = (PASS == 0) ? (g_xinh + (size_t)batch * NN * 128)
                                     : (g_g   + (size_t)batch * FFd * 128);
    uint2 hr = *(const uint2*)(srcb + (size_t)c * 32 + q * 4);
    __half2 h0 = *(__half2*)&hr.x;
    __half2 h1 = *(__half2*)&hr.y;
    float2 f0 = __half22float2(h0);
    float2 f1 = __half22float2(h1);
    float4 x = make_float4(f0.x * v, f0.y * v, f1.x * v, f1.y * v);
    float* dst = (PASS == 0) ? (g_t0 + (size_t)batch * FFd * 128)
                             : (g_t1 + (size_t)batch * NN * 128);
    asm volatile("red.global.add.v4.f32 [%0], {%1, %2, %3, %4};"
                 :: "l"(dst + (size_t)r * 32 + q * 4), "f"(x.x), "f"(x.y), "f"(x.z), "f"(x.w)
                 : "memory");
}

// ---- finalize BN + fold into linear; emit fp16 hi/lo weights + fused bias ----
template <int PASS>
__global__ void finalize_fold_kernel(const float* __restrict__ gamma, const float* __restrict__ beta,
                                     const float* __restrict__ w, const float* __restrict__ bias,
                                     int M) {
    __shared__ float a_s[256], sh_s[256];
    const double* stats = (PASS == 0) ? g_stats0 : g_stats1;
    __half* whi = (PASS == 0) ? g_w0hi : g_w1hi;
    __half* wlo = (PASS == 0) ? g_w0lo : g_w1lo;
    float* bp = (PASS == 0) ? g_b0p : g_b1p;
    int j = threadIdx.x;
    double invM = 1.0 / (double)M;
    double mu   = stats[j] * invM;
    double var  = stats[256 + j] * invM - mu * mu;
    float a  = gamma[j] * rsqrtf((float)var + 1e-5f);
    float sh = beta[j] - (float)mu * a;
    a_s[j] = a; sh_s[j] = sh;
    __syncthreads();
    for (int idx = j; idx < 128 * 256; idx += 256) {
        float wv = w[idx] * a_s[idx & 255];
        __half hi = __float2half_rn(wv);
        __half lo = __float2half_rn(wv - __half2float(hi));
        whi[idx] = hi; wlo[idx] = lo;
    }
    if (j < 128) {
        float s = bias[j];
        const float* wr = w + j * 256;
        for (int q = 0; q < 256; q++) s += sh_s[q] * wr[q];
        bp[j] = s;
    }
}

// ---------------- fp16 HMMA GEMM, 2-chain (A·Whi + A·Wlo), cp.async 2-stage --------
// K chunks of 64 fp16 (128B SW128 rows). stage s: A 16KB | Whi 16KB | Wlo 16KB.
#define STAGE_SZ 49152
#define SMEM_SZ  (1024 + 2 * STAGE_SZ)   // 99328

template <int PASS>
__global__ void __launch_bounds__(256, 2)
gemm_mma_kernel(const float* __restrict__ resid, float* __restrict__ out, int M) {
    extern __shared__ char smem[];
    const uint4* A0h = (const uint4*)(PASS == 0 ? g_finh : g_xinh);
    const uint4* A1h = (const uint4*)(PASS == 0 ? g_t0h : g_t1h);
    const uint4* Whi = (const uint4*)(PASS == 0 ? g_w0hi : g_w1hi);
    const uint4* Wlo = (const uint4*)(PASS == 0 ? g_w0lo : g_w1lo);
    const float* bp = (PASS == 0) ? g_b0p : g_b1p;

    uint32_t sb = smem_u32(smem);
    int tid  = threadIdx.x;
    int wid  = tid >> 5;
    int lane = tid & 31;
    int m0   = blockIdx.x * 128;
    int wm   = (wid & 3) * 32;
    int wn   = (wid >> 2) * 64;

    if (tid < 128) *(float*)(smem + tid * 4) = bp[tid];

    float acc[2][8][4];
#pragma unroll
    for (int mt = 0; mt < 2; mt++)
#pragma unroll
        for (int nt = 0; nt < 8; nt++)
#pragma unroll
            for (int e = 0; e < 4; e++) acc[mt][nt][e] = 0.f;

    int lrow = (lane & 7) + ((lane >> 3) & 1) * 8;
    int lkg  = lane >> 4;

    // stage chunk ch (K=64 slice) into stage buffer s: 12 cp.async per thread
    auto stage_chunk = [&](int ch, int s) {
        const uint4* Ah = (ch < 2) ? A0h : A1h;
        int cb = (ch & 1) * 8;          // granule base within A's 16-granule row
        int wb = ch * 8;                // granule base within W's 32-granule row
        uint32_t abase = sb + 1024 + s * STAGE_SZ;
        uint32_t hbase = abase + 16384;
        uint32_t lbase = abase + 32768;
#pragma unroll
        for (int i = 0; i < 4; i++) {
            int idx = tid + i * 256;    // 0..1023
            int row = idx >> 3;         // 0..127
            int u   = idx & 7;          // 0..7
            uint32_t soff = SW128((uint32_t)(row * 128 + u * 16));
            bool ok = (m0 + row < M);
            size_t gi = ok ? ((size_t)(m0 + row) * 16 + cb + u) : 0;
            cpa16(abase + soff, Ah + gi, ok ? 16 : 0);
            cpa16(hbase + soff, Whi + row * 32 + wb + u, 16);
            cpa16(lbase + soff, Wlo + row * 32 + wb + u, 16);
        }
    };

    stage_chunk(0, 0);
    CP_COMMIT();

    for (int ch = 0; ch < 4; ch++) {
        if (ch < 3) { stage_chunk(ch + 1, (ch + 1) & 1); CP_COMMIT(); cp_wait<1>(); }
        else        { cp_wait<0>(); }
        __syncthreads();

        uint32_t abase = sb + 1024 + (ch & 1) * STAGE_SZ;
        uint32_t hbase = abase + 16384;
        uint32_t lbase = abase + 32768;
#pragma unroll
        for (int ks = 0; ks < 4; ks++) {
            int g = ks * 2 + lkg;       // granule 0..7
            uint32_t a[2][4];
#pragma unroll
            for (int mt = 0; mt < 2; mt++) {
                uint32_t rb = (uint32_t)((wm + mt * 16 + lrow) * 128);
                ldsm4(a[mt], abase + SW128(rb + g * 16));
            }
#pragma unroll
            for (int nt2 = 0; nt2 < 4; nt2++) {
                uint32_t rb = (uint32_t)((wn + nt2 * 16 + lrow) * 128);
                uint32_t bh[4], bl[4];
                ldsm4(bh, hbase + SW128(rb + g * 16));
                ldsm4(bl, lbase + SW128(rb + g * 16));
#pragma unroll
                for (int mt = 0; mt < 2; mt++) {
                    mma16816h(acc[mt][nt2 * 2 + 0], a[mt], bh[0], bh[2]);
                    mma16816h(acc[mt][nt2 * 2 + 1], a[mt], bh[1], bh[3]);
                    mma16816h(acc[mt][nt2 * 2 + 0], a[mt], bl[0], bl[2]);
                    mma16816h(acc[mt][nt2 * 2 + 1], a[mt], bl[1], bl[3]);
                }
            }
        }
        __syncthreads();
    }

    const float* bias_s = (const float*)smem;
    int r0 = lane >> 2;
    int cp = (lane & 3) * 2;
#pragma unroll
    for (int mt = 0; mt < 2; mt++) {
#pragma unroll
        for (int nt = 0; nt < 8; nt++) {
            int col = wn + nt * 8 + cp;
            float b0 = bias_s[col], b1 = bias_s[col + 1];
#pragma unroll
            for (int h = 0; h < 2; h++) {
                int rr = m0 + wm + mt * 16 + r0 + h * 8;
                if (rr >= M) continue;
                size_t base = (size_t)rr * 128 + col;
                float v0 = acc[mt][nt][h * 2 + 0] + b0;
                float v1 = acc[mt][nt][h * 2 + 1] + b1;
                if (PASS == 1) {
                    float2 rd = *(const float2*)(resid + base);
                    v0 += rd.x; v1 += rd.y;
                }
                *(float2*)(out + base) = make_float2(v0, v1);
                if (PASS == 0) {
                    __half2 gh = __float22half2_rn(make_float2(elu1(v0), elu1(v1)));
                    *(uint32_t*)(g_g + base) = *(uint32_t*)&gh;
                }
            }
        }
    }
}

// ---------------- launch ----------------
extern "C" void kernel_launch(void* const* d_in, const int* in_sizes, int n_in,
                              void* d_out, int out_size) {
    const int*   Di_rows  = (const int*)d_in[0];
    const int*   Di_cols  = (const int*)d_in[1];
    const float* Di_vals  = (const float*)d_in[2];
    const int*   DiA_rows = (const int*)d_in[3];
    const int*   DiA_cols = (const int*)d_in[4];
    const float* DiA_vals = (const float*)d_in[5];
    const float* v_in     = (const float*)d_in[6];
    const float* f_in     = (const float*)d_in[7];
    const float* bn0_g    = (const float*)d_in[8];
    const float* bn0_b    = (const float*)d_in[9];
    const float* fc0_w    = (const float*)d_in[10];
    const float* fc0_b    = (const float*)d_in[11];
    const float* bn1_g    = (const float*)d_in[12];
    const float* bn1_b    = (const float*)d_in[13];
    const float* fc1_w    = (const float*)d_in[14];
    const float* fc1_b    = (const float*)d_in[15];

    float* out_v = (float*)d_out;                 // v + v_out : [4,30000,128]
    float* out_f = out_v + SZ_V;                  // f_out     : [4,60000,128]

    const int T = 256;
    const int nv4 = (int)(SZ_V / 4);
    const int nf4 = (int)(SZ_F / 4);
    const int spGrid = (NNZk / 4 * 32) / T;       // 22500 blocks

    cudaFuncSetAttribute(gemm_mma_kernel<0>, cudaFuncAttributeMaxDynamicSharedMemorySize, SMEM_SZ);
    cudaFuncSetAttribute(gemm_mma_kernel<1>, cudaFuncAttributeMaxDynamicSharedMemorySize, SMEM_SZ);

    // 0) zero stats
    zero_stats_kernel<<<1, 256>>>();

    // 1) elu inputs + first-half BN stats + fp16 emit
    elu_stats_kernel<0><<<1024, T>>>((const float4*)v_in, nv4);
    elu_stats_kernel<1><<<1024, T>>>((const float4*)f_in, nf4);

    // 2) spbmm1 per batch: zero slice then scatter
    for (int b = 0; b < BB; b++) {
        zero_slice_kernel<0><<<(FFd * 32 + T - 1) / T, T>>>(b);
        spbmm_kernel<0><<<spGrid, T>>>(Di_rows, Di_cols, Di_vals, b);
    }

    // 3) BN0 second-half stats + t0 fp16 + fold into fc0
    halfstats_kernel<0><<<1024, T>>>(nf4);
    finalize_fold_kernel<0><<<1, 256>>>(bn0_g, bn0_b, fc0_w, fc0_b, BB * FFd);

    // 4) gemm0: f_out (+ fp16 elu copy into g_g)
    gemm_mma_kernel<0><<<(BB * FFd + 127) / 128, 256, SMEM_SZ>>>(nullptr, out_f, BB * FFd);

    // 5) spbmm2 per batch
    for (int b = 0; b < BB; b++) {
        zero_slice_kernel<1><<<(NN * 32 + T - 1) / T, T>>>(b);
        spbmm_kernel<1><<<spGrid, T>>>(DiA_rows, DiA_cols, DiA_vals, b);
    }

    // 6) BN1 second-half stats + t1 fp16 + fold into fc1
    halfstats_kernel<1><<<1024, T>>>(nv4);
    finalize_fold_kernel<1><<<1, 256>>>(bn1_g, bn1_b, fc1_w, fc1_b, BB * NN);

    // 7) gemm1: out_v = v + linear(...)
    gemm_mma_kernel<1><<<(BB * NN + 127) / 128, 256, SMEM_SZ>>>(v_in, out_v, BB * NN);
}

// round 17
// speedup vs baseline: 1.3138x; 1.0951x over previous
#include <cuda_runtime.h>
#include <cuda_fp16.h>
#include <math.h>
#include <stdint.h>

// Problem constants
#define BB   4
#define NN   30000
#define FFd  60000
#define NNZk 720000

static const size_t SZ_V = (size_t)BB * NN * 128;   // 15,360,000
static const size_t SZ_F = (size_t)BB * FFd * 128;  // 30,720,000

// ---------------- scratch (static device arrays) ----------------
__device__ __half g_xinh[15360000];                   // elu(v) fp16
__device__ __half g_finh[30720000];                   // elu(f) fp16
__device__ float  g_t0 [30720000];                    // spbmm1 out f32
__device__ __half g_t0h[30720000];                    // t0 fp16
__device__ __half g_g  [30720000];                    // elu(f_out) fp16 (spbmm2 src)
__device__ float  g_t1 [15360000];                    // spbmm2 out f32
__device__ __half g_t1h[15360000];                    // t1 fp16
__device__ double g_stats0[512];
__device__ double g_stats1[512];
__device__ __half g_w0h[32768];                       // BN-folded fc0 weight fp16
__device__ __half g_w1h[32768];
__device__ float  g_b0p[128];
__device__ float  g_b1p[128];

// ---------------- helpers ----------------
__device__ __forceinline__ uint32_t smem_u32(const void* p) {
    uint32_t a;
    asm("{ .reg .u64 t; cvta.to.shared.u64 t, %1; cvt.u32.u64 %0, t; }" : "=r"(a) : "l"(p));
    return a;
}

#define SW128(o) ((o) ^ (((o) >> 3) & 0x70))

__device__ __forceinline__ float elu1(float x) { return x > 0.f ? x : expm1f(x); }

__device__ __forceinline__ void ldsm4(uint32_t* d, uint32_t addr) {
    asm volatile("ldmatrix.sync.aligned.m8n8.x4.shared.b16 {%0,%1,%2,%3}, [%4];"
                 : "=r"(d[0]), "=r"(d[1]), "=r"(d[2]), "=r"(d[3]) : "r"(addr));
}

__device__ __forceinline__ void mma16816h(float* c, const uint32_t* a, uint32_t b0, uint32_t b1) {
    asm volatile("mma.sync.aligned.m16n8k16.row.col.f32.f16.f16.f32 "
                 "{%0,%1,%2,%3}, {%4,%5,%6,%7}, {%8,%9}, {%0,%1,%2,%3};"
                 : "+f"(c[0]), "+f"(c[1]), "+f"(c[2]), "+f"(c[3])
                 : "r"(a[0]), "r"(a[1]), "r"(a[2]), "r"(a[3]), "r"(b0), "r"(b1));
}

__device__ __forceinline__ void cpa16(uint32_t smem, const uint4* gptr, int sz) {
    asm volatile("cp.async.cg.shared.global [%0], [%1], 16, %2;"
                 :: "r"(smem), "l"(gptr), "r"(sz) : "memory");
}
#define CP_COMMIT() asm volatile("cp.async.commit_group;" ::: "memory")
template <int N> __device__ __forceinline__ void cp_wait() {
    asm volatile("cp.async.wait_group %0;" :: "n"(N) : "memory");
}

// pack 4 floats -> 4 fp16 (uint2)
__device__ __forceinline__ uint2 pack_h4(float4 v) {
    __half2 a = __float22half2_rn(make_float2(v.x, v.y));
    __half2 b = __float22half2_rn(make_float2(v.z, v.w));
    uint2 r;
    r.x = *(uint32_t*)&a;
    r.y = *(uint32_t*)&b;
    return r;
}

// ---------------- zero kernels ----------------
__global__ void zero_stats_kernel() {
    int i = threadIdx.x;
    ((double2*)g_stats0)[i] = make_double2(0.0, 0.0);
    ((double2*)g_stats1)[i] = make_double2(0.0, 0.0);
}

template <int WHICH>
__global__ void zero_slice_kernel(int batch) {
    int i = blockIdx.x * blockDim.x + threadIdx.x;
    int n4 = (WHICH == 0) ? FFd * 32 : NN * 32;
    if (i >= n4) return;
    float4* p = (WHICH == 0) ? ((float4*)g_t0 + (size_t)batch * (FFd * 32))
                             : ((float4*)g_t1 + (size_t)batch * (NN * 32));
    p[i] = make_float4(0.f, 0.f, 0.f, 0.f);
}

// ---------------- fused elu + column stats + fp16 emit -----------------------------
template <int WHICH>
__global__ void elu_stats_kernel(const float4* __restrict__ in, int n4) {
    __shared__ float rs[8][32][4], rq[8][32][4];
    double* stats = (WHICH == 0) ? g_stats1 : g_stats0;
    uint2* outh = (uint2*)(WHICH == 0 ? g_xinh : g_finh);
    int tid = threadIdx.x;
    float s[4] = {0.f, 0.f, 0.f, 0.f}, q2[4] = {0.f, 0.f, 0.f, 0.f};
    for (int i = blockIdx.x * blockDim.x + tid; i < n4; i += gridDim.x * blockDim.x) {
        float4 v = in[i];
        v.x = elu1(v.x); v.y = elu1(v.y); v.z = elu1(v.z); v.w = elu1(v.w);
        outh[i] = pack_h4(v);
        s[0] += v.x; q2[0] += v.x * v.x;
        s[1] += v.y; q2[1] += v.y * v.y;
        s[2] += v.z; q2[2] += v.z * v.z;
        s[3] += v.w; q2[3] += v.w * v.w;
    }
    int cq = tid & 31, rt = tid >> 5;
#pragma unroll
    for (int e = 0; e < 4; e++) { rs[rt][cq][e] = s[e]; rq[rt][cq][e] = q2[e]; }
    __syncthreads();
    if (tid < 128) {
        int e = tid & 3, c = tid >> 2;
        float t = 0.f;
#pragma unroll
        for (int r = 0; r < 8; r++) t += rs[r][c][e];
        atomicAdd(&stats[c * 4 + e], (double)t);
    } else {
        int t2 = tid - 128;
        int e = t2 & 3, c = t2 >> 2;
        float t = 0.f;
#pragma unroll
        for (int r = 0; r < 8; r++) t += rq[r][c][e];
        atomicAdd(&stats[256 + c * 4 + e], (double)t);
    }
}

// ---- second-half stats over t0 / t1 + fp16 emit ----
template <int PASS>
__global__ void halfstats_kernel(int n4) {
    __shared__ float rs[8][32][4], rq[8][32][4];
    const float4* src = (PASS == 0) ? (const float4*)g_t0 : (const float4*)g_t1;
    uint2* outh = (uint2*)(PASS == 0 ? g_t0h : g_t1h);
    double* stats = (PASS == 0) ? g_stats0 : g_stats1;
    int tid = threadIdx.x;
    float s[4] = {0.f, 0.f, 0.f, 0.f}, q2[4] = {0.f, 0.f, 0.f, 0.f};
    for (int i = blockIdx.x * blockDim.x + tid; i < n4; i += gridDim.x * blockDim.x) {
        float4 v = src[i];
        outh[i] = pack_h4(v);
        s[0] += v.x; q2[0] += v.x * v.x;
        s[1] += v.y; q2[1] += v.y * v.y;
        s[2] += v.z; q2[2] += v.z * v.z;
        s[3] += v.w; q2[3] += v.w * v.w;
    }
    int cq = tid & 31, rt = tid >> 5;
#pragma unroll
    for (int e = 0; e < 4; e++) { rs[rt][cq][e] = s[e]; rq[rt][cq][e] = q2[e]; }
    __syncthreads();
    if (tid < 128) {
        int e = tid & 3, c = tid >> 2;
        float t = 0.f;
#pragma unroll
        for (int r = 0; r < 8; r++) t += rs[r][c][e];
        atomicAdd(&stats[128 + c * 4 + e], (double)t);
    } else {
        int t2 = tid - 128;
        int e = t2 & 3, c = t2 >> 2;
        float t = 0.f;
#pragma unroll
        for (int r = 0; r < 8; r++) t += rq[r][c][e];
        atomicAdd(&stats[384 + c * 4 + e], (double)t);
    }
}

// ---------------- sparse COO spmm, one batch per launch (L2-resident dst) ----------
template <int PASS>
__global__ void spbmm_kernel(const int* __restrict__ rows, const int* __restrict__ cols,
                             const float* __restrict__ vals, int batch) {
    int gw   = (blockIdx.x * blockDim.x + threadIdx.x) >> 5;
    int lane = threadIdx.x & 31;
    int e    = gw * 4 + (lane >> 3);
    int q    = lane & 7;
    if (e >= NNZk) return;
    int   r = rows[e];
    int   c = cols[e];
    float v = vals[e];
    const __half* srcb = (PASS == 0) ? (g_xinh + (size_t)batch * NN * 128)
                                     : (g_g   + (size_t)batch * FFd * 128);
    uint2 hr = *(const uint2*)(srcb + (size_t)c * 32 + q * 4);
    __half2 h0 = *(__half2*)&hr.x;
    __half2 h1 = *(__half2*)&hr.y;
    float2 f0 = __half22float2(h0);
    float2 f1 = __half22float2(h1);
    float4 x = make_float4(f0.x * v, f0.y * v, f1.x * v, f1.y * v);
    float* dst = (PASS == 0) ? (g_t0 + (size_t)batch * FFd * 128)
                             : (g_t1 + (size_t)batch * NN * 128);
    asm volatile("red.global.add.v4.f32 [%0], {%1, %2, %3, %4};"
                 :: "l"(dst + (size_t)r * 32 + q * 4), "f"(x.x), "f"(x.y), "f"(x.z), "f"(x.w)
                 : "memory");
}

// ---- finalize BN + fold into linear; emit fp16 weights + fused bias ----
template <int PASS>
__global__ void finalize_fold_kernel(const float* __restrict__ gamma, const float* __restrict__ beta,
                                     const float* __restrict__ w, const float* __restrict__ bias,
                                     int M) {
    __shared__ float a_s[256], sh_s[256];
    const double* stats = (PASS == 0) ? g_stats0 : g_stats1;
    __half* wh = (PASS == 0) ? g_w0h : g_w1h;
    float* bp = (PASS == 0) ? g_b0p : g_b1p;
    int j = threadIdx.x;
    double invM = 1.0 / (double)M;
    double mu   = stats[j] * invM;
    double var  = stats[256 + j] * invM - mu * mu;
    float a  = gamma[j] * rsqrtf((float)var + 1e-5f);
    float sh = beta[j] - (float)mu * a;
    a_s[j] = a; sh_s[j] = sh;
    __syncthreads();
    for (int idx = j; idx < 128 * 256; idx += 256) {
        wh[idx] = __float2half_rn(w[idx] * a_s[idx & 255]);
    }
    if (j < 128) {
        float s = bias[j];
        const float* wr = w + j * 256;
        for (int q = 0; q < 256; q++) s += sh_s[q] * wr[q];
        bp[j] = s;
    }
}

// ---------------- fp16 HMMA GEMM, 1-chain (A·W), cp.async 2-stage ------------------
// K chunks of 64 fp16 (128B SW128 rows). stage s: A 16KB | W 16KB.
#define STAGE_SZ 32768
#define SMEM_SZ  (1024 + 2 * STAGE_SZ)   // 66560

template <int PASS>
__global__ void __launch_bounds__(256, 2)
gemm_mma_kernel(const float* __restrict__ resid, float* __restrict__ out, int M) {
    extern __shared__ char smem[];
    const uint4* A0h = (const uint4*)(PASS == 0 ? g_finh : g_xinh);
    const uint4* A1h = (const uint4*)(PASS == 0 ? g_t0h : g_t1h);
    const uint4* Wh  = (const uint4*)(PASS == 0 ? g_w0h : g_w1h);
    const float* bp = (PASS == 0) ? g_b0p : g_b1p;

    uint32_t sb = smem_u32(smem);
    int tid  = threadIdx.x;
    int wid  = tid >> 5;
    int lane = tid & 31;
    int m0   = blockIdx.x * 128;
    int wm   = (wid & 3) * 32;
    int wn   = (wid >> 2) * 64;

    if (tid < 128) *(float*)(smem + tid * 4) = bp[tid];

    float acc[2][8][4];
#pragma unroll
    for (int mt = 0; mt < 2; mt++)
#pragma unroll
        for (int nt = 0; nt < 8; nt++)
#pragma unroll
            for (int e = 0; e < 4; e++) acc[mt][nt][e] = 0.f;

    int lrow = (lane & 7) + ((lane >> 3) & 1) * 8;
    int lkg  = lane >> 4;

    // stage chunk ch (K=64 slice) into stage buffer s: 8 cp.async per thread
    auto stage_chunk = [&](int ch, int s) {
        const uint4* Ah = (ch < 2) ? A0h : A1h;
        int cb = (ch & 1) * 8;          // granule base within A's 16-granule row
        int wb = ch * 8;                // granule base within W's 32-granule row
        uint32_t abase = sb + 1024 + s * STAGE_SZ;
        uint32_t wbase = abase + 16384;
#pragma unroll
        for (int i = 0; i < 4; i++) {
            int idx = tid + i * 256;    // 0..1023
            int row = idx >> 3;         // 0..127
            int u   = idx & 7;          // 0..7
            uint32_t soff = SW128((uint32_t)(row * 128 + u * 16));
            bool ok = (m0 + row < M);
            size_t gi = ok ? ((size_t)(m0 + row) * 16 + cb + u) : 0;
            cpa16(abase + soff, Ah + gi, ok ? 16 : 0);
            cpa16(wbase + soff, Wh + row * 32 + wb + u, 16);
        }
    };

    stage_chunk(0, 0);
    CP_COMMIT();

    for (int ch = 0; ch < 4; ch++) {
        if (ch < 3) { stage_chunk(ch + 1, (ch + 1) & 1); CP_COMMIT(); cp_wait<1>(); }
        else        { cp_wait<0>(); }
        __syncthreads();

        uint32_t abase = sb + 1024 + (ch & 1) * STAGE_SZ;
        uint32_t wbase = abase + 16384;
#pragma unroll
        for (int ks = 0; ks < 4; ks++) {
            int g = ks * 2 + lkg;       // granule 0..7
            uint32_t a[2][4];
#pragma unroll
            for (int mt = 0; mt < 2; mt++) {
                uint32_t rb = (uint32_t)((wm + mt * 16 + lrow) * 128);
                ldsm4(a[mt], abase + SW128(rb + g * 16));
            }
#pragma unroll
            for (int nt2 = 0; nt2 < 4; nt2++) {
                uint32_t rb = (uint32_t)((wn + nt2 * 16 + lrow) * 128);
                uint32_t bh[4];
                ldsm4(bh, wbase + SW128(rb + g * 16));
#pragma unroll
                for (int mt = 0; mt < 2; mt++) {
                    mma16816h(acc[mt][nt2 * 2 + 0], a[mt], bh[0], bh[2]);
                    mma16816h(acc[mt][nt2 * 2 + 1], a[mt], bh[1], bh[3]);
                }
            }
        }
        __syncthreads();
    }

    const float* bias_s = (const float*)smem;
    int r0 = lane >> 2;
    int cp = (lane & 3) * 2;
#pragma unroll
    for (int mt = 0; mt < 2; mt++) {
#pragma unroll
        for (int nt = 0; nt < 8; nt++) {
            int col = wn + nt * 8 + cp;
            float b0 = bias_s[col], b1 = bias_s[col + 1];
#pragma unroll
            for (int h = 0; h < 2; h++) {
                int rr = m0 + wm + mt * 16 + r0 + h * 8;
                if (rr >= M) continue;
                size_t base = (size_t)rr * 128 + col;
                float v0 = acc[mt][nt][h * 2 + 0] + b0;
                float v1 = acc[mt][nt][h * 2 + 1] + b1;
                if (PASS == 1) {
                    float2 rd = *(const float2*)(resid + base);
                    v0 += rd.x; v1 += rd.y;
                }
                *(float2*)(out + base) = make_float2(v0, v1);
                if (PASS == 0) {
                    __half2 gh = __float22half2_rn(make_float2(elu1(v0), elu1(v1)));
                    *(uint32_t*)(g_g + base) = *(uint32_t*)&gh;
                }
            }
        }
    }
}

// ---------------- launch ----------------
extern "C" void kernel_launch(void* const* d_in, const int* in_sizes, int n_in,
                              void* d_out, int out_size) {
    const int*   Di_rows  = (const int*)d_in[0];
    const int*   Di_cols  = (const int*)d_in[1];
    const float* Di_vals  = (const float*)d_in[2];
    const int*   DiA_rows = (const int*)d_in[3];
    const int*   DiA_cols = (const int*)d_in[4];
    const float* DiA_vals = (const float*)d_in[5];
    const float* v_in     = (const float*)d_in[6];
    const float* f_in     = (const float*)d_in[7];
    const float* bn0_g    = (const float*)d_in[8];
    const float* bn0_b    = (const float*)d_in[9];
    const float* fc0_w    = (const float*)d_in[10];
    const float* fc0_b    = (const float*)d_in[11];
    const float* bn1_g    = (const float*)d_in[12];
    const float* bn1_b    = (const float*)d_in[13];
    const float* fc1_w    = (const float*)d_in[14];
    const float* fc1_b    = (const float*)d_in[15];

    float* out_v = (float*)d_out;                 // v + v_out : [4,30000,128]
    float* out_f = out_v + SZ_V;                  // f_out     : [4,60000,128]

    const int T = 256;
    const int nv4 = (int)(SZ_V / 4);
    const int nf4 = (int)(SZ_F / 4);
    const int spGrid = (NNZk / 4 * 32) / T;       // 22500 blocks

    cudaFuncSetAttribute(gemm_mma_kernel<0>, cudaFuncAttributeMaxDynamicSharedMemorySize, SMEM_SZ);
    cudaFuncSetAttribute(gemm_mma_kernel<1>, cudaFuncAttributeMaxDynamicSharedMemorySize, SMEM_SZ);

    // 0) zero stats
    zero_stats_kernel<<<1, 256>>>();

    // 1) elu inputs + first-half BN stats + fp16 emit
    elu_stats_kernel<0><<<1024, T>>>((const float4*)v_in, nv4);
    elu_stats_kernel<1><<<1024, T>>>((const float4*)f_in, nf4);

    // 2) spbmm1 per batch: zero slice then scatter
    for (int b = 0; b < BB; b++) {
        zero_slice_kernel<0><<<(FFd * 32 + T - 1) / T, T>>>(b);
        spbmm_kernel<0><<<spGrid, T>>>(Di_rows, Di_cols, Di_vals, b);
    }

    // 3) BN0 second-half stats + t0 fp16 + fold into fc0
    halfstats_kernel<0><<<1024, T>>>(nf4);
    finalize_fold_kernel<0><<<1, 256>>>(bn0_g, bn0_b, fc0_w, fc0_b, BB * FFd);

    // 4) gemm0: f_out (+ fp16 elu copy into g_g)
    gemm_mma_kernel<0><<<(BB * FFd + 127) / 128, 256, SMEM_SZ>>>(nullptr, out_f, BB * FFd);

    // 5) spbmm2 per batch
    for (int b = 0; b < BB; b++) {
        zero_slice_kernel<1><<<(NN * 32 + T - 1) / T, T>>>(b);
        spbmm_kernel<1><<<spGrid, T>>>(DiA_rows, DiA_cols, DiA_vals, b);
    }

    // 6) BN1 second-half stats + t1 fp16 + fold into fc1
    halfstats_kernel<1><<<1024, T>>>(nv4);
    finalize_fold_kernel<1><<<1, 256>>>(bn1_g, bn1_b, fc1_w, fc1_b, BB * NN);

    // 7) gemm1: out_v = v + linear(...)
    gemm_mma_kernel<1><<<(BB * NN + 127) / 128, 256, SMEM_SZ>>>(v_in, out_v, BB * NN);
}